// round 2
// baseline (speedup 1.0000x reference)
#include <cuda_runtime.h>
#include <math.h>

#define Bc 8
#define Tc 256
#define Nn 118
#define Fc 3
#define Dc 128
#define Ec 372
#define Gc (Bc*Tc)          // 2048 graphs
#define Mc (Gc*Nn)          // 241664 rows

// ---------------- scratch (device globals; no allocation allowed) ----------------
__device__ float g_H[(size_t)Mc*Dc];     // ~124MB
__device__ float g_X[(size_t)Mc*Dc];     // ~124MB
__device__ float g_emb[Gc*Dc];
__device__ float g_xg0[(size_t)Gc*4*Dc]; // precomputed x@Wih0^T + biases
__device__ float g_final[Bc*Dc];
__device__ int   g_rowoff[Nn+1];
__device__ int   g_csrsrc[Ec];
__device__ float g_csrnorm[Ec];
__device__ float g_invdeg[Nn];

__device__ __forceinline__ float sigmoidf_(float x){ return 1.0f/(1.0f+expf(-x)); }
__device__ __forceinline__ float siluf_(float x){ return x/(1.0f+expf(-x)); }

// ---------------- prep: decode edge_index (int32 or int64), build CSR ----------------
__global__ void k_prep(const int* __restrict__ ei) {
    __shared__ int ssrc[Ec], sdst[Ec];
    if (threadIdx.x != 0) return;
    // detect dtype: int64 little-endian => all high words (odd int32 slots of first E
    // entries) are zero. Values are in [0,118), so this is unambiguous in practice.
    bool is64 = true;
    for (int i = 1; i < 2*Ec; i += 2) { if (ei[i] != 0) { is64 = false; break; } }
    for (int e = 0; e < Ec; e++) {
        if (is64) { ssrc[e] = ei[2*e]; sdst[e] = ei[2*(Ec+e)]; }
        else      { ssrc[e] = ei[e];   sdst[e] = ei[Ec+e];     }
    }
    float deg[Nn];
    for (int n = 0; n < Nn; n++) deg[n] = 1.0f;
    for (int e = 0; e < Ec; e++) deg[sdst[e]] += 1.0f;
    float inv[Nn];
    for (int n = 0; n < Nn; n++) {
        g_invdeg[n] = 1.0f/deg[n];
        inv[n] = 1.0f/sqrtf(deg[n]);
    }
    int cnt[Nn];
    for (int n = 0; n < Nn; n++) cnt[n] = 0;
    for (int e = 0; e < Ec; e++) cnt[sdst[e]]++;
    int off = 0;
    for (int n = 0; n < Nn; n++) { g_rowoff[n] = off; off += cnt[n]; cnt[n] = g_rowoff[n]; }
    g_rowoff[Nn] = off;
    for (int e = 0; e < Ec; e++) {
        int d = sdst[e]; int p = cnt[d]++;
        g_csrsrc[p]  = ssrc[e];
        g_csrnorm[p] = inv[ssrc[e]] * inv[d];
    }
}

// ---------------- layer 1: H = (snap*scale+shift) @ W1   (K=3) ----------------
__global__ void __launch_bounds__(128) k_layer1(const float* __restrict__ snap,
        const float* __restrict__ scale, const float* __restrict__ shift,
        const float* __restrict__ W1, float* __restrict__ H) {
    __shared__ float xs[64*3];
    __shared__ float sW[3*128];
    int t = threadIdx.x;
    size_t m0 = (size_t)blockIdx.x * 64;
    for (int i = t; i < 192; i += 128) {
        int f = i - (i/3)*3;
        xs[i] = snap[m0*3 + i]*scale[f] + shift[f];
    }
    for (int i = t; i < 384; i += 128) sW[i] = W1[i];
    __syncthreads();
    float w0 = sW[t], w1 = sW[128+t], w2 = sW[256+t];
    #pragma unroll 4
    for (int r = 0; r < 64; r++) {
        float v = xs[r*3]*w0 + xs[r*3+1]*w1 + xs[r*3+2]*w2;
        H[(m0+r)*Dc + t] = v;
    }
}

// ---------------- aggregation + bias + SiLU (per graph, CSR gather) ----------------
__global__ void __launch_bounds__(128) k_agg(const float* __restrict__ Hin,
        float* __restrict__ out, const float* __restrict__ bias) {
    extern __shared__ float Hs[];            // 118*128 floats = 60416 B
    __shared__ int   soff[Nn+1];
    __shared__ int   ssrc[Ec];
    __shared__ float snorm[Ec];
    __shared__ float sinvd[Nn];
    int t = threadIdx.x;
    size_t base = (size_t)blockIdx.x * (Nn*Dc);
    for (int n = 0; n < Nn; n++) Hs[n*Dc + t] = Hin[base + n*Dc + t];
    for (int i = t; i <= Nn; i += 128) soff[i] = g_rowoff[i];
    for (int i = t; i < Ec; i += 128) { ssrc[i] = g_csrsrc[i]; snorm[i] = g_csrnorm[i]; }
    if (t < Nn) sinvd[t] = g_invdeg[t];
    __syncthreads();
    float b = bias[t];
    for (int n = 0; n < Nn; n++) {
        float acc = Hs[n*Dc + t] * sinvd[n];
        int e0 = soff[n], e1 = soff[n+1];
        for (int e = e0; e < e1; e++)
            acc += Hs[ssrc[e]*Dc + t] * snorm[e];
        float v = acc + b;
        out[base + n*Dc + t] = siluf_(v);
    }
}

// ---------------- fp32 GEMM: C[M,128] = A[M,128] @ W[128,128] ----------------
__global__ void __launch_bounds__(256,2) k_gemm(const float* __restrict__ A,
        const float* __restrict__ W, float* __restrict__ C) {
    __shared__ float As[16][132];   // transposed A tile, padded
    __shared__ float Ws[16][128];
    int tid = threadIdx.x;
    int tr = tid >> 4, tc = tid & 15;
    size_t bm = (size_t)blockIdx.x * 128;
    float acc[8][8];
    #pragma unroll
    for (int i = 0; i < 8; i++)
        #pragma unroll
        for (int j = 0; j < 8; j++) acc[i][j] = 0.f;

    for (int k0 = 0; k0 < 128; k0 += 16) {
        #pragma unroll
        for (int l = 0; l < 2; l++) {
            int idx = tid + l*256;
            int row = idx >> 2, c4 = idx & 3;
            float4 v = *(const float4*)(A + (bm+row)*128 + k0 + c4*4);
            As[c4*4+0][row] = v.x; As[c4*4+1][row] = v.y;
            As[c4*4+2][row] = v.z; As[c4*4+3][row] = v.w;
        }
        #pragma unroll
        for (int l = 0; l < 2; l++) {
            int idx = tid + l*256;
            int row = idx >> 5, c4 = idx & 31;
            *(float4*)(&Ws[row][c4*4]) = *(const float4*)(W + (k0+row)*128 + c4*4);
        }
        __syncthreads();
        #pragma unroll
        for (int k = 0; k < 16; k++) {
            float4 a0 = *(float4*)&As[k][tr*8];
            float4 a1 = *(float4*)&As[k][tr*8+4];
            float4 w0 = *(float4*)&Ws[k][tc*8];
            float4 w1 = *(float4*)&Ws[k][tc*8+4];
            float am[8] = {a0.x,a0.y,a0.z,a0.w,a1.x,a1.y,a1.z,a1.w};
            float wn[8] = {w0.x,w0.y,w0.z,w0.w,w1.x,w1.y,w1.z,w1.w};
            #pragma unroll
            for (int i = 0; i < 8; i++)
                #pragma unroll
                for (int j = 0; j < 8; j++)
                    acc[i][j] += am[i]*wn[j];
        }
        __syncthreads();
    }
    #pragma unroll
    for (int i = 0; i < 8; i++) {
        size_t r = bm + tr*8 + i;
        float4 o0 = make_float4(acc[i][0],acc[i][1],acc[i][2],acc[i][3]);
        float4 o1 = make_float4(acc[i][4],acc[i][5],acc[i][6],acc[i][7]);
        *(float4*)(C + r*128 + tc*8)     = o0;
        *(float4*)(C + r*128 + tc*8 + 4) = o1;
    }
}

// ---------------- mean over nodes ----------------
__global__ void __launch_bounds__(128) k_mean(const float* __restrict__ X) {
    int t = threadIdx.x; int g = blockIdx.x;
    const float* p = X + (size_t)g*Nn*Dc + t;
    float acc = 0.f;
    for (int n = 0; n < Nn; n++) acc += p[n*Dc];
    g_emb[g*Dc + t] = acc * (1.0f/(float)Nn);
}

// ---------------- xg0 = emb @ Wih0^T + bih0 + bhh0 ----------------
__global__ void __launch_bounds__(512) k_xg0(const float* __restrict__ Wih0,
        const float* __restrict__ bih0, const float* __restrict__ bhh0) {
    __shared__ float es[16*128];
    int j = threadIdx.x;
    int m0 = blockIdx.x * 16;
    for (int i = j; i < 2048; i += 512) es[i] = g_emb[m0*128 + i];
    __syncthreads();
    const float4* wr = (const float4*)(Wih0 + (size_t)j*128);
    float acc[16];
    #pragma unroll
    for (int r = 0; r < 16; r++) acc[r] = 0.f;
    #pragma unroll 4
    for (int k4 = 0; k4 < 32; k4++) {
        float4 w = wr[k4];
        #pragma unroll
        for (int r = 0; r < 16; r++) {
            float4 e = *(const float4*)&es[r*128 + k4*4];
            acc[r] += w.x*e.x + w.y*e.y + w.z*e.z + w.w*e.w;
        }
    }
    float bb = bih0[j] + bhh0[j];
    #pragma unroll
    for (int r = 0; r < 16; r++)
        g_xg0[(size_t)(m0+r)*512 + j] = acc[r] + bb;
}

// ---------------- LSTM: one block per batch, 512 sequential steps ----------------
__global__ void __launch_bounds__(512) k_lstm(const float* __restrict__ Whh0,
        const float* __restrict__ Wih1, const float* __restrict__ Whh1,
        const float* __restrict__ bih1, const float* __restrict__ bhh1) {
    __shared__ float sh0[128], sh1[128], sg[512];
    int j = threadIdx.x;
    int b = blockIdx.x;
    const float4* w0 = (const float4*)(Whh0 + (size_t)j*128);
    const float4* wi = (const float4*)(Wih1 + (size_t)j*128);
    const float4* wh = (const float4*)(Whh1 + (size_t)j*128);
    float bias1 = bih1[j] + bhh1[j];
    float c0 = 0.f, c1 = 0.f;
    if (j < 128) { sh0[j] = 0.f; sh1[j] = 0.f; }
    __syncthreads();
    const float* xg = g_xg0 + (size_t)b*256*512;
    const float4* h0v = (const float4*)sh0;
    const float4* h1v = (const float4*)sh1;
    for (int t = 0; t < 256; t++) {
        // layer 0 gate j
        float4 a = make_float4(0,0,0,0);
        #pragma unroll
        for (int k = 0; k < 32; k++) {
            float4 w = w0[k]; float4 h = h0v[k];
            a.x += w.x*h.x; a.y += w.y*h.y; a.z += w.z*h.z; a.w += w.w*h.w;
        }
        sg[j] = xg[t*512 + j] + ((a.x + a.y) + (a.z + a.w));
        __syncthreads();
        if (j < 128) {
            float ig = sigmoidf_(sg[j]);
            float fg = sigmoidf_(sg[128+j]);
            float gg = tanhf(sg[256+j]);
            float og = sigmoidf_(sg[384+j]);
            c0 = fg*c0 + ig*gg;
            sh0[j] = og * tanhf(c0);
        }
        __syncthreads();
        // layer 1 gate j
        float4 a1 = make_float4(0,0,0,0);
        #pragma unroll
        for (int k = 0; k < 32; k++) {
            float4 w = wi[k]; float4 h = h0v[k];
            a1.x += w.x*h.x; a1.y += w.y*h.y; a1.z += w.z*h.z; a1.w += w.w*h.w;
        }
        #pragma unroll
        for (int k = 0; k < 32; k++) {
            float4 w = wh[k]; float4 h = h1v[k];
            a1.x += w.x*h.x; a1.y += w.y*h.y; a1.z += w.z*h.z; a1.w += w.w*h.w;
        }
        sg[j] = bias1 + ((a1.x + a1.y) + (a1.z + a1.w));
        __syncthreads();
        if (j < 128) {
            float ig = sigmoidf_(sg[j]);
            float fg = sigmoidf_(sg[128+j]);
            float gg = tanhf(sg[256+j]);
            float og = sigmoidf_(sg[384+j]);
            c1 = fg*c1 + ig*gg;
            sh1[j] = og * tanhf(c1);
        }
        __syncthreads();
    }
    if (j < 128) g_final[b*128 + j] = sh1[j];
}

// ---------------- head MLP ----------------
__global__ void __launch_bounds__(128) k_head(const float* __restrict__ hW1, const float* __restrict__ hb1,
        const float* __restrict__ hW2, const float* __restrict__ hb2,
        const float* __restrict__ hW3, const float* __restrict__ hb3,
        float* __restrict__ out) {
    __shared__ float sf[8*128], s1[8*128], s2[8*64];
    int t = threadIdx.x;
    for (int i = t; i < 1024; i += 128) sf[i] = g_final[i];
    __syncthreads();
    {
        int d = t;
        for (int b = 0; b < 8; b++) {
            float acc = hb1[d];
            for (int k = 0; k < 128; k++) acc += sf[b*128+k]*hW1[k*128+d];
            s1[b*128+d] = siluf_(acc);
        }
    }
    __syncthreads();
    if (t < 64) {
        int e = t;
        for (int b = 0; b < 8; b++) {
            float acc = hb2[e];
            for (int k = 0; k < 128; k++) acc += s1[b*128+k]*hW2[k*64+e];
            s2[b*64+e] = siluf_(acc);
        }
    }
    __syncthreads();
    if (t < 16) {
        int b = t >> 1, o = t & 1;
        float acc = hb3[o];
        for (int k = 0; k < 64; k++) acc += s2[b*64+k]*hW3[k*2+o];
        float sp = fmaxf(acc, 0.f) + log1pf(expf(-fabsf(acc)));
        out[b*2+o] = sp + 1e-6f;
    }
}

// ---------------- launch ----------------
extern "C" void kernel_launch(void* const* d_in, const int* in_sizes, int n_in,
                              void* d_out, int out_size) {
    const float* snap  = (const float*)d_in[0];
    const int*   ei    = (const int*)  d_in[1];
    const float* scale = (const float*)d_in[2];
    const float* shift = (const float*)d_in[3];
    const float* W1    = (const float*)d_in[4];
    const float* b1    = (const float*)d_in[5];
    const float* W2    = (const float*)d_in[6];
    const float* b2    = (const float*)d_in[7];
    const float* W3    = (const float*)d_in[8];
    const float* b3    = (const float*)d_in[9];
    const float* Wih0  = (const float*)d_in[10];
    const float* Whh0  = (const float*)d_in[11];
    const float* bih0  = (const float*)d_in[12];
    const float* bhh0  = (const float*)d_in[13];
    const float* Wih1  = (const float*)d_in[14];
    const float* Whh1  = (const float*)d_in[15];
    const float* bih1  = (const float*)d_in[16];
    const float* bhh1  = (const float*)d_in[17];
    const float* hW1   = (const float*)d_in[18];
    const float* hb1   = (const float*)d_in[19];
    const float* hW2   = (const float*)d_in[20];
    const float* hb2   = (const float*)d_in[21];
    const float* hW3   = (const float*)d_in[22];
    const float* hb3   = (const float*)d_in[23];
    float* out = (float*)d_out;

    float *H, *X;
    cudaGetSymbolAddress((void**)&H, g_H);
    cudaGetSymbolAddress((void**)&X, g_X);

    const int aggSmem = Nn*Dc*(int)sizeof(float); // 60416
    cudaFuncSetAttribute(k_agg, cudaFuncAttributeMaxDynamicSharedMemorySize, aggSmem);

    k_prep<<<1, 32>>>(ei);
    k_layer1<<<Mc/64, 128>>>(snap, scale, shift, W1, H);
    k_agg<<<Gc, 128, aggSmem>>>(H, X, b1);
    k_gemm<<<Mc/128, 256>>>(X, W2, H);
    k_agg<<<Gc, 128, aggSmem>>>(H, X, b2);
    k_gemm<<<Mc/128, 256>>>(X, W3, H);
    k_agg<<<Gc, 128, aggSmem>>>(H, X, b3);
    k_mean<<<Gc, 128>>>(X);
    k_xg0<<<Gc/16, 512>>>(Wih0, bih0, bhh0);
    k_lstm<<<Bc, 512>>>(Whh0, Wih1, Whh1, bih1, bhh1);
    k_head<<<1, 128>>>(hW1, hb1, hW2, hb2, hW3, hb3, out);
}

// round 4
// speedup vs baseline: 2.7858x; 2.7858x over previous
#include <cuda_runtime.h>
#include <stdint.h>
#include <math.h>

#define Bc 8
#define Tc 256
#define Nn 118
#define Fc 3
#define Dc 128
#define Ec 372
#define Gc (Bc*Tc)          // 2048 graphs
#define Mc (Gc*Nn)          // 241664 rows
#define CLN 4               // cluster size for LSTM

// ---------------- scratch (device globals; no allocation allowed) ----------------
__device__ float g_H[(size_t)Mc*Dc];     // ~124MB
__device__ float g_X[(size_t)Mc*Dc];     // ~124MB
__device__ float g_emb[Gc*Dc];
__device__ float g_xg0[(size_t)Gc*4*Dc]; // precomputed x@Wih0^T + biases (PERMUTED layout)
__device__ float g_final[Bc*Dc];
__device__ int   g_rowoff[Nn+1];
__device__ int   g_csrsrc[Ec];
__device__ float g_csrnorm[Ec];
__device__ float g_invdeg[Nn];

__device__ __forceinline__ float sigmoidf_(float x){ return 1.0f/(1.0f+expf(-x)); }
__device__ __forceinline__ float siluf_(float x){ return x/(1.0f+expf(-x)); }

__device__ __forceinline__ uint32_t s2u(const void* p){
    uint32_t a;
    asm("{ .reg .u64 t; cvta.to.shared.u64 t, %1; cvt.u32.u64 %0, t; }" : "=r"(a) : "l"(p));
    return a;
}
__device__ __forceinline__ void st_cluster_f32(uint32_t laddr, uint32_t peer, float v){
    asm volatile("{ .reg .b32 ra; mapa.shared::cluster.u32 ra, %0, %1; st.shared::cluster.f32 [ra], %2; }"
                 :: "r"(laddr), "r"(peer), "f"(v) : "memory");
}
__device__ __forceinline__ void mbar_arrive_cluster(uint32_t laddr, uint32_t peer){
    asm volatile("{ .reg .b32 ra; mapa.shared::cluster.u32 ra, %0, %1; "
                 "mbarrier.arrive.release.cluster.shared::cluster.b64 _, [ra]; }"
                 :: "r"(laddr), "r"(peer) : "memory");
}
__device__ __forceinline__ void mbar_wait_acq(uint32_t addr, uint32_t parity){
    asm volatile("{\n\t"
        ".reg .pred P;\n\t"
        "WL%=:\n\t"
        "mbarrier.try_wait.parity.acquire.cluster.shared::cta.b64 P, [%0], %1, 0x989680;\n\t"
        "@!P bra WL%=;\n\t"
        "}" :: "r"(addr), "r"(parity) : "memory");
}
__device__ __forceinline__ void fence_cluster(){
    asm volatile("fence.acq_rel.cluster;" ::: "memory");
}

// ---------------- prep: decode edge_index (int32 or int64), build CSR ----------------
__global__ void k_prep(const int* __restrict__ ei) {
    __shared__ int ssrc[Ec], sdst[Ec];
    if (threadIdx.x != 0) return;
    bool is64 = true;
    for (int i = 1; i < 2*Ec; i += 2) { if (ei[i] != 0) { is64 = false; break; } }
    for (int e = 0; e < Ec; e++) {
        if (is64) { ssrc[e] = ei[2*e]; sdst[e] = ei[2*(Ec+e)]; }
        else      { ssrc[e] = ei[e];   sdst[e] = ei[Ec+e];     }
    }
    float deg[Nn];
    for (int n = 0; n < Nn; n++) deg[n] = 1.0f;
    for (int e = 0; e < Ec; e++) deg[sdst[e]] += 1.0f;
    float inv[Nn];
    for (int n = 0; n < Nn; n++) {
        g_invdeg[n] = 1.0f/deg[n];
        inv[n] = 1.0f/sqrtf(deg[n]);
    }
    int cnt[Nn];
    for (int n = 0; n < Nn; n++) cnt[n] = 0;
    for (int e = 0; e < Ec; e++) cnt[sdst[e]]++;
    int off = 0;
    for (int n = 0; n < Nn; n++) { g_rowoff[n] = off; off += cnt[n]; cnt[n] = g_rowoff[n]; }
    g_rowoff[Nn] = off;
    for (int e = 0; e < Ec; e++) {
        int d = sdst[e]; int p = cnt[d]++;
        g_csrsrc[p]  = ssrc[e];
        g_csrnorm[p] = inv[ssrc[e]] * inv[d];
    }
}

// ---------------- layer 1: H = (snap*scale+shift) @ W1   (K=3) ----------------
__global__ void __launch_bounds__(128) k_layer1(const float* __restrict__ snap,
        const float* __restrict__ scale, const float* __restrict__ shift,
        const float* __restrict__ W1, float* __restrict__ H) {
    __shared__ float xs[64*3];
    __shared__ float sW[3*128];
    int t = threadIdx.x;
    size_t m0 = (size_t)blockIdx.x * 64;
    for (int i = t; i < 192; i += 128) {
        int f = i - (i/3)*3;
        xs[i] = snap[m0*3 + i]*scale[f] + shift[f];
    }
    for (int i = t; i < 384; i += 128) sW[i] = W1[i];
    __syncthreads();
    float w0 = sW[t], w1 = sW[128+t], w2 = sW[256+t];
    #pragma unroll 4
    for (int r = 0; r < 64; r++) {
        float v = xs[r*3]*w0 + xs[r*3+1]*w1 + xs[r*3+2]*w2;
        H[(m0+r)*Dc + t] = v;
    }
}

// ---------------- aggregation + bias + SiLU (per graph, CSR gather) ----------------
__global__ void __launch_bounds__(128) k_agg(const float* __restrict__ Hin,
        float* __restrict__ out, const float* __restrict__ bias) {
    extern __shared__ float Hs[];            // 118*128 floats = 60416 B
    __shared__ int   soff[Nn+1];
    __shared__ int   ssrc[Ec];
    __shared__ float snorm[Ec];
    __shared__ float sinvd[Nn];
    int t = threadIdx.x;
    size_t base = (size_t)blockIdx.x * (Nn*Dc);
    for (int n = 0; n < Nn; n++) Hs[n*Dc + t] = Hin[base + n*Dc + t];
    for (int i = t; i <= Nn; i += 128) soff[i] = g_rowoff[i];
    for (int i = t; i < Ec; i += 128) { ssrc[i] = g_csrsrc[i]; snorm[i] = g_csrnorm[i]; }
    if (t < Nn) sinvd[t] = g_invdeg[t];
    __syncthreads();
    float b = bias[t];
    for (int n = 0; n < Nn; n++) {
        float acc = Hs[n*Dc + t] * sinvd[n];
        int e0 = soff[n], e1 = soff[n+1];
        for (int e = e0; e < e1; e++)
            acc += Hs[ssrc[e]*Dc + t] * snorm[e];
        float v = acc + b;
        out[base + n*Dc + t] = siluf_(v);
    }
}

// ---------------- fp32 GEMM: C[M,128] = A[M,128] @ W[128,128] ----------------
__global__ void __launch_bounds__(256,2) k_gemm(const float* __restrict__ A,
        const float* __restrict__ W, float* __restrict__ C) {
    __shared__ float As[16][132];   // transposed A tile, padded
    __shared__ float Ws[16][128];
    int tid = threadIdx.x;
    int tr = tid >> 4, tc = tid & 15;
    size_t bm = (size_t)blockIdx.x * 128;
    float acc[8][8];
    #pragma unroll
    for (int i = 0; i < 8; i++)
        #pragma unroll
        for (int j = 0; j < 8; j++) acc[i][j] = 0.f;

    for (int k0 = 0; k0 < 128; k0 += 16) {
        #pragma unroll
        for (int l = 0; l < 2; l++) {
            int idx = tid + l*256;
            int row = idx >> 2, c4 = idx & 3;
            float4 v = *(const float4*)(A + (bm+row)*128 + k0 + c4*4);
            As[c4*4+0][row] = v.x; As[c4*4+1][row] = v.y;
            As[c4*4+2][row] = v.z; As[c4*4+3][row] = v.w;
        }
        #pragma unroll
        for (int l = 0; l < 2; l++) {
            int idx = tid + l*256;
            int row = idx >> 5, c4 = idx & 31;
            *(float4*)(&Ws[row][c4*4]) = *(const float4*)(W + (k0+row)*128 + c4*4);
        }
        __syncthreads();
        #pragma unroll
        for (int k = 0; k < 16; k++) {
            float4 a0 = *(float4*)&As[k][tr*8];
            float4 a1 = *(float4*)&As[k][tr*8+4];
            float4 w0 = *(float4*)&Ws[k][tc*8];
            float4 w1 = *(float4*)&Ws[k][tc*8+4];
            float am[8] = {a0.x,a0.y,a0.z,a0.w,a1.x,a1.y,a1.z,a1.w};
            float wn[8] = {w0.x,w0.y,w0.z,w0.w,w1.x,w1.y,w1.z,w1.w};
            #pragma unroll
            for (int i = 0; i < 8; i++)
                #pragma unroll
                for (int j = 0; j < 8; j++)
                    acc[i][j] += am[i]*wn[j];
        }
        __syncthreads();
    }
    #pragma unroll
    for (int i = 0; i < 8; i++) {
        size_t r = bm + tr*8 + i;
        float4 o0 = make_float4(acc[i][0],acc[i][1],acc[i][2],acc[i][3]);
        float4 o1 = make_float4(acc[i][4],acc[i][5],acc[i][6],acc[i][7]);
        *(float4*)(C + r*128 + tc*8)     = o0;
        *(float4*)(C + r*128 + tc*8 + 4) = o1;
    }
}

// ---------------- mean over nodes ----------------
__global__ void __launch_bounds__(128) k_mean(const float* __restrict__ X) {
    int t = threadIdx.x; int g = blockIdx.x;
    const float* p = X + (size_t)g*Nn*Dc + t;
    float acc = 0.f;
    for (int n = 0; n < Nn; n++) acc += p[n*Dc];
    g_emb[g*Dc + t] = acc * (1.0f/(float)Nn);
}

// ---------------- xg0 = emb @ Wih0^T + bih0 + bhh0 (PERMUTED output layout) ----------------
// gate row j = q*128 + e (q=gate type, e=element). owner CTA r=e/32, local row q*32+e%32.
// store at p = r*128 + q*32 + (e%32) so CTA r reads [r*128 + t] coalesced.
__global__ void __launch_bounds__(512) k_xg0(const float* __restrict__ Wih0,
        const float* __restrict__ bih0, const float* __restrict__ bhh0) {
    __shared__ float es[16*128];
    int j = threadIdx.x;
    int m0 = blockIdx.x * 16;
    for (int i = j; i < 2048; i += 512) es[i] = g_emb[m0*128 + i];
    __syncthreads();
    const float4* wr = (const float4*)(Wih0 + (size_t)j*128);
    float acc[16];
    #pragma unroll
    for (int r = 0; r < 16; r++) acc[r] = 0.f;
    #pragma unroll 4
    for (int k4 = 0; k4 < 32; k4++) {
        float4 w = wr[k4];
        #pragma unroll
        for (int r = 0; r < 16; r++) {
            float4 e = *(const float4*)&es[r*128 + k4*4];
            acc[r] += w.x*e.x + w.y*e.y + w.z*e.z + w.w*e.w;
        }
    }
    float bb = bih0[j] + bhh0[j];
    int q = j >> 7, e = j & 127;
    int cr = e >> 5, l = e & 31;
    int pidx = cr*128 + q*32 + l;
    #pragma unroll
    for (int r = 0; r < 16; r++)
        g_xg0[(size_t)(m0+r)*512 + pidx] = acc[r] + bb;
}

// ---------------- LSTM: 4-CTA cluster per batch, weights resident in smem ----------------
// CTA r of cluster b holds rows {q*128 + r*32 + l} of Whh0/Wih1/Whh1 in smem (padded 132 f/row).
// Per step: each thread computes one gate row dot; warp0 owns h elements r*32+lane and the
// cell states; new h pushed to all 4 CTAs via DSMEM; mbarrier release/acquire per layer.
__global__ void __launch_bounds__(128,1) __cluster_dims__(CLN,1,1)
k_lstm2(const float* __restrict__ Whh0, const float* __restrict__ Wih1,
        const float* __restrict__ Whh1,
        const float* __restrict__ bih1, const float* __restrict__ bhh1) {
    extern __shared__ float sw[];                 // 3 * 128 * 132 floats
    __shared__ float h0buf[2][128];
    __shared__ float h1buf[2][128];
    __shared__ float sg[128];
    __shared__ __align__(8) unsigned long long mbs[2];

    int t    = threadIdx.x;
    int lane = t & 31;
    int q    = t >> 5;
    int cta  = blockIdx.x & (CLN-1);
    int b    = blockIdx.x / CLN;
    int grow = q*128 + cta*32 + lane;

    float4* s0 = (float4*)sw;          // Whh0 slice: 128 rows x 33 float4
    float4* si = s0 + 128*33;          // Wih1 slice
    float4* sh = si + 128*33;          // Whh1 slice
    {
        const float4* g0 = (const float4*)(Whh0 + (size_t)grow*128);
        const float4* gi = (const float4*)(Wih1 + (size_t)grow*128);
        const float4* gh = (const float4*)(Whh1 + (size_t)grow*128);
        #pragma unroll 4
        for (int k = 0; k < 32; k++) {
            s0[t*33+k] = g0[k];
            si[t*33+k] = gi[k];
            sh[t*33+k] = gh[k];
        }
    }
    h0buf[0][t] = 0.f; h1buf[0][t] = 0.f;
    uint32_t mb0a = s2u(&mbs[0]), mb1a = s2u(&mbs[1]);
    uint32_t h0a = s2u(h0buf), h1a = s2u(h1buf);
    if (t == 0) {
        asm volatile("mbarrier.init.shared.b64 [%0], %1;" :: "r"(mb0a), "r"(CLN) : "memory");
        asm volatile("mbarrier.init.shared.b64 [%0], %1;" :: "r"(mb1a), "r"(CLN) : "memory");
    }
    __syncthreads();
    asm volatile("barrier.cluster.arrive.aligned;" ::: "memory");
    asm volatile("barrier.cluster.wait.aligned;"   ::: "memory");

    float bias1 = bih1[grow] + bhh1[grow];
    float c0 = 0.f, c1 = 0.f, hlast = 0.f;
    const float* xg = g_xg0 + (size_t)b*256*512 + cta*128 + t;
    const float4* w0r = s0 + t*33;
    const float4* wir = si + t*33;
    const float4* whr = sh + t*33;

    for (int s = 0; s < 256; s++) {
        int p = s & 1;
        float xv = xg[s*512];

        // ---- layer 0 gate: dot(Whh0_row, h0_old) ----
        {
            const float4* hv = (const float4*)h0buf[p];
            float4 a = make_float4(0,0,0,0), bacc = make_float4(0,0,0,0);
            #pragma unroll
            for (int k = 0; k < 32; k += 2) {
                float4 w = w0r[k],   h = hv[k];
                a.x += w.x*h.x; a.y += w.y*h.y; a.z += w.z*h.z; a.w += w.w*h.w;
                float4 w2 = w0r[k+1], h2 = hv[k+1];
                bacc.x += w2.x*h2.x; bacc.y += w2.y*h2.y; bacc.z += w2.z*h2.z; bacc.w += w2.w*h2.w;
            }
            sg[t] = xv + ((a.x+a.y)+(a.z+a.w)) + ((bacc.x+bacc.y)+(bacc.z+bacc.w));
        }
        __syncthreads();
        if (t < 32) {
            float ig = sigmoidf_(sg[t]);
            float fg = sigmoidf_(sg[32+t]);
            float gg = tanhf(sg[64+t]);
            float og = sigmoidf_(sg[96+t]);
            c0 = fg*c0 + ig*gg;
            float hv0 = og * tanhf(c0);
            uint32_t dst = h0a + (uint32_t)(((p^1)*128 + cta*32 + t)*4);
            #pragma unroll
            for (int peer = 0; peer < CLN; peer++) st_cluster_f32(dst, peer, hv0);
            __syncwarp();
            if (t == 0) {
                fence_cluster();
                #pragma unroll
                for (int peer = 0; peer < CLN; peer++) mbar_arrive_cluster(mb0a, peer);
            }
        }
        // ---- overlap mbarrier wait with independent dot(Whh1_row, h1_old) ----
        float4 aA = make_float4(0,0,0,0), aA2 = make_float4(0,0,0,0);
        {
            const float4* hv = (const float4*)h1buf[p];
            #pragma unroll
            for (int k = 0; k < 32; k += 2) {
                float4 w = whr[k],   h = hv[k];
                aA.x += w.x*h.x; aA.y += w.y*h.y; aA.z += w.z*h.z; aA.w += w.w*h.w;
                float4 w2 = whr[k+1], h2 = hv[k+1];
                aA2.x += w2.x*h2.x; aA2.y += w2.y*h2.y; aA2.z += w2.z*h2.z; aA2.w += w2.w*h2.w;
            }
        }
        mbar_wait_acq(mb0a, (uint32_t)p);
        // ---- dot(Wih1_row, h0_new) ----
        {
            const float4* hv = (const float4*)h0buf[p^1];
            float4 aB = make_float4(0,0,0,0), aB2 = make_float4(0,0,0,0);
            #pragma unroll
            for (int k = 0; k < 32; k += 2) {
                float4 w = wir[k],   h = hv[k];
                aB.x += w.x*h.x; aB.y += w.y*h.y; aB.z += w.z*h.z; aB.w += w.w*h.w;
                float4 w2 = wir[k+1], h2 = hv[k+1];
                aB2.x += w2.x*h2.x; aB2.y += w2.y*h2.y; aB2.z += w2.z*h2.z; aB2.w += w2.w*h2.w;
            }
            sg[t] = bias1
                  + ((aA.x+aA.y)+(aA.z+aA.w)) + ((aA2.x+aA2.y)+(aA2.z+aA2.w))
                  + ((aB.x+aB.y)+(aB.z+aB.w)) + ((aB2.x+aB2.y)+(aB2.z+aB2.w));
        }
        __syncthreads();
        if (t < 32) {
            float ig = sigmoidf_(sg[t]);
            float fg = sigmoidf_(sg[32+t]);
            float gg = tanhf(sg[64+t]);
            float og = sigmoidf_(sg[96+t]);
            c1 = fg*c1 + ig*gg;
            float hv1 = og * tanhf(c1);
            hlast = hv1;
            uint32_t dst = h1a + (uint32_t)(((p^1)*128 + cta*32 + t)*4);
            #pragma unroll
            for (int peer = 0; peer < CLN; peer++) st_cluster_f32(dst, peer, hv1);
            __syncwarp();
            if (t == 0) {
                fence_cluster();
                #pragma unroll
                for (int peer = 0; peer < CLN; peer++) mbar_arrive_cluster(mb1a, peer);
            }
        }
        mbar_wait_acq(mb1a, (uint32_t)p);
    }
    if (t < 32) g_final[b*128 + cta*32 + t] = hlast;
}

// ---------------- head MLP ----------------
__global__ void __launch_bounds__(128) k_head(const float* __restrict__ hW1, const float* __restrict__ hb1,
        const float* __restrict__ hW2, const float* __restrict__ hb2,
        const float* __restrict__ hW3, const float* __restrict__ hb3,
        float* __restrict__ out) {
    __shared__ float sf[8*128], s1[8*128], s2[8*64];
    int t = threadIdx.x;
    for (int i = t; i < 1024; i += 128) sf[i] = g_final[i];
    __syncthreads();
    {
        int d = t;
        for (int b = 0; b < 8; b++) {
            float acc = hb1[d];
            for (int k = 0; k < 128; k++) acc += sf[b*128+k]*hW1[k*128+d];
            s1[b*128+d] = siluf_(acc);
        }
    }
    __syncthreads();
    if (t < 64) {
        int e = t;
        for (int b = 0; b < 8; b++) {
            float acc = hb2[e];
            for (int k = 0; k < 128; k++) acc += s1[b*128+k]*hW2[k*64+e];
            s2[b*64+e] = siluf_(acc);
        }
    }
    __syncthreads();
    if (t < 16) {
        int b = t >> 1, o = t & 1;
        float acc = hb3[o];
        for (int k = 0; k < 64; k++) acc += s2[b*64+k]*hW3[k*2+o];
        float sp = fmaxf(acc, 0.f) + log1pf(expf(-fabsf(acc)));
        out[b*2+o] = sp + 1e-6f;
    }
}

// ---------------- launch ----------------
extern "C" void kernel_launch(void* const* d_in, const int* in_sizes, int n_in,
                              void* d_out, int out_size) {
    const float* snap  = (const float*)d_in[0];
    const int*   ei    = (const int*)  d_in[1];
    const float* scale = (const float*)d_in[2];
    const float* shift = (const float*)d_in[3];
    const float* W1    = (const float*)d_in[4];
    const float* b1    = (const float*)d_in[5];
    const float* W2    = (const float*)d_in[6];
    const float* b2    = (const float*)d_in[7];
    const float* W3    = (const float*)d_in[8];
    const float* b3    = (const float*)d_in[9];
    const float* Wih0  = (const float*)d_in[10];
    const float* Whh0  = (const float*)d_in[11];
    const float* bih0  = (const float*)d_in[12];
    const float* bhh0  = (const float*)d_in[13];
    const float* Wih1  = (const float*)d_in[14];
    const float* Whh1  = (const float*)d_in[15];
    const float* bih1  = (const float*)d_in[16];
    const float* bhh1  = (const float*)d_in[17];
    const float* hW1   = (const float*)d_in[18];
    const float* hb1   = (const float*)d_in[19];
    const float* hW2   = (const float*)d_in[20];
    const float* hb2   = (const float*)d_in[21];
    const float* hW3   = (const float*)d_in[22];
    const float* hb3   = (const float*)d_in[23];
    float* out = (float*)d_out;

    float *H, *X;
    cudaGetSymbolAddress((void**)&H, g_H);
    cudaGetSymbolAddress((void**)&X, g_X);

    const int aggSmem  = Nn*Dc*(int)sizeof(float);       // 60416
    const int lstmSmem = 3*128*132*(int)sizeof(float);   // 202752
    cudaFuncSetAttribute(k_agg,   cudaFuncAttributeMaxDynamicSharedMemorySize, aggSmem);
    cudaFuncSetAttribute(k_lstm2, cudaFuncAttributeMaxDynamicSharedMemorySize, lstmSmem);

    k_prep<<<1, 32>>>(ei);
    k_layer1<<<Mc/64, 128>>>(snap, scale, shift, W1, H);
    k_agg<<<Gc, 128, aggSmem>>>(H, X, b1);
    k_gemm<<<Mc/128, 256>>>(X, W2, H);
    k_agg<<<Gc, 128, aggSmem>>>(H, X, b2);
    k_gemm<<<Mc/128, 256>>>(X, W3, H);
    k_agg<<<Gc, 128, aggSmem>>>(H, X, b3);
    k_mean<<<Gc, 128>>>(X);
    k_xg0<<<Gc/16, 512>>>(Wih0, bih0, bhh0);
    k_lstm2<<<Bc*CLN, 128, lstmSmem>>>(Whh0, Wih1, Whh1, bih1, bhh1);
    k_head<<<1, 128>>>(hW1, hb1, hW2, hb2, hW3, hb3, out);
}

// round 5
// speedup vs baseline: 3.6493x; 1.3100x over previous
#include <cuda_runtime.h>
#include <stdint.h>
#include <math.h>

#define Bc 8
#define Tc 256
#define Nn 118
#define Fc 3
#define Dc 128
#define Ec 372
#define Gc (Bc*Tc)          // 2048 graphs
#define Mc (Gc*Nn)          // 241664 rows
#define CLN 4               // cluster size for LSTM

// ---------------- scratch (device globals; no allocation allowed) ----------------
__device__ float g_H[(size_t)Mc*Dc];     // ~124MB
__device__ float g_X[(size_t)Mc*Dc];     // ~124MB
__device__ float g_emb[Gc*Dc];
__device__ float g_xg0[(size_t)Gc*4*Dc]; // precomputed x@Wih0^T + biases (PERMUTED layout)
__device__ float g_final[Bc*Dc];
__device__ int   g_rowoff[Nn+1];
__device__ int   g_csrsrc[Ec];
__device__ float g_csrnorm[Ec];
__device__ float g_invdeg[Nn];

__device__ __forceinline__ float sigmoidf_(float x){ return 1.0f/(1.0f+expf(-x)); }
__device__ __forceinline__ float siluf_(float x){ return x/(1.0f+expf(-x)); }

__device__ __forceinline__ uint32_t s2u(const void* p){
    uint32_t a;
    asm("{ .reg .u64 t; cvta.to.shared.u64 t, %1; cvt.u32.u64 %0, t; }" : "=r"(a) : "l"(p));
    return a;
}
__device__ __forceinline__ void st_cluster_f32(uint32_t laddr, uint32_t peer, float v){
    asm volatile("{ .reg .b32 ra; mapa.shared::cluster.u32 ra, %0, %1; st.shared::cluster.f32 [ra], %2; }"
                 :: "r"(laddr), "r"(peer), "f"(v) : "memory");
}
__device__ __forceinline__ void mbar_arrive_cluster(uint32_t laddr, uint32_t peer){
    asm volatile("{ .reg .b32 ra; mapa.shared::cluster.u32 ra, %0, %1; "
                 "mbarrier.arrive.release.cluster.shared::cluster.b64 _, [ra]; }"
                 :: "r"(laddr), "r"(peer) : "memory");
}
__device__ __forceinline__ void mbar_wait_acq(uint32_t addr, uint32_t parity){
    asm volatile("{\n\t"
        ".reg .pred P;\n\t"
        "WL%=:\n\t"
        "mbarrier.try_wait.parity.acquire.cluster.shared::cta.b64 P, [%0], %1, 0x989680;\n\t"
        "@!P bra WL%=;\n\t"
        "}" :: "r"(addr), "r"(parity) : "memory");
}

// ---------------- prep: decode edge_index (int32 or int64), build CSR ----------------
__global__ void k_prep(const int* __restrict__ ei) {
    if (threadIdx.x != 0) return;
    int ssrc[Ec], sdst[Ec];
    bool is64 = true;
    for (int i = 1; i < 2*Ec; i += 2) { if (ei[i] != 0) { is64 = false; break; } }
    for (int e = 0; e < Ec; e++) {
        if (is64) { ssrc[e] = ei[2*e]; sdst[e] = ei[2*(Ec+e)]; }
        else      { ssrc[e] = ei[e];   sdst[e] = ei[Ec+e];     }
    }
    float deg[Nn];
    for (int n = 0; n < Nn; n++) deg[n] = 1.0f;
    for (int e = 0; e < Ec; e++) deg[sdst[e]] += 1.0f;
    float inv[Nn];
    for (int n = 0; n < Nn; n++) {
        g_invdeg[n] = 1.0f/deg[n];
        inv[n] = 1.0f/sqrtf(deg[n]);
    }
    int cnt[Nn];
    for (int n = 0; n < Nn; n++) cnt[n] = 0;
    for (int e = 0; e < Ec; e++) cnt[sdst[e]]++;
    int off = 0;
    for (int n = 0; n < Nn; n++) { g_rowoff[n] = off; off += cnt[n]; cnt[n] = g_rowoff[n]; }
    g_rowoff[Nn] = off;
    for (int e = 0; e < Ec; e++) {
        int d = sdst[e]; int p = cnt[d]++;
        g_csrsrc[p]  = ssrc[e];
        g_csrnorm[p] = inv[ssrc[e]] * inv[d];
    }
}

// ---------------- fused layer1 GEMM (K=3) + aggregation + SiLU ----------------
__global__ void __launch_bounds__(128) k_l1agg(const float* __restrict__ snap,
        const float* __restrict__ scale, const float* __restrict__ shift,
        const float* __restrict__ W1, const float* __restrict__ bias,
        float* __restrict__ out) {
    extern __shared__ float Hs[];            // 118*128 floats
    __shared__ float xs[Nn*Fc];
    __shared__ float sW[Fc*Dc];
    __shared__ int   soff[Nn+1];
    __shared__ int   ssrc[Ec];
    __shared__ float snorm[Ec];
    __shared__ float sinvd[Nn];
    int t = threadIdx.x;
    int g = blockIdx.x;
    for (int i = t; i < Nn*Fc; i += 128) {
        int f = i - (i/3)*3;
        xs[i] = snap[(size_t)g*Nn*Fc + i]*scale[f] + shift[f];
    }
    for (int i = t; i < Fc*Dc; i += 128) sW[i] = W1[i];
    for (int i = t; i <= Nn; i += 128) soff[i] = g_rowoff[i];
    for (int i = t; i < Ec; i += 128) { ssrc[i] = g_csrsrc[i]; snorm[i] = g_csrnorm[i]; }
    if (t < Nn) sinvd[t] = g_invdeg[t];
    __syncthreads();
    float w0 = sW[t], w1 = sW[128+t], w2 = sW[256+t];
    #pragma unroll 2
    for (int n = 0; n < Nn; n++)
        Hs[n*Dc + t] = xs[n*3]*w0 + xs[n*3+1]*w1 + xs[n*3+2]*w2;
    __syncthreads();
    float b = bias[t];
    size_t base = (size_t)g * (Nn*Dc);
    for (int n = 0; n < Nn; n++) {
        float acc = Hs[n*Dc + t] * sinvd[n];
        int e0 = soff[n], e1 = soff[n+1];
        for (int e = e0; e < e1; e++)
            acc += Hs[ssrc[e]*Dc + t] * snorm[e];
        out[base + n*Dc + t] = siluf_(acc + b);
    }
}

// ---------------- aggregation + bias + SiLU (per graph, CSR gather) ----------------
__global__ void __launch_bounds__(128) k_agg(const float* __restrict__ Hin,
        float* __restrict__ out, const float* __restrict__ bias) {
    extern __shared__ float Hs[];            // 118*128 floats = 60416 B
    __shared__ int   soff[Nn+1];
    __shared__ int   ssrc[Ec];
    __shared__ float snorm[Ec];
    __shared__ float sinvd[Nn];
    int t = threadIdx.x;
    size_t base = (size_t)blockIdx.x * (Nn*Dc);
    for (int n = 0; n < Nn; n++) Hs[n*Dc + t] = Hin[base + n*Dc + t];
    for (int i = t; i <= Nn; i += 128) soff[i] = g_rowoff[i];
    for (int i = t; i < Ec; i += 128) { ssrc[i] = g_csrsrc[i]; snorm[i] = g_csrnorm[i]; }
    if (t < Nn) sinvd[t] = g_invdeg[t];
    __syncthreads();
    float b = bias[t];
    for (int n = 0; n < Nn; n++) {
        float acc = Hs[n*Dc + t] * sinvd[n];
        int e0 = soff[n], e1 = soff[n+1];
        for (int e = e0; e < e1; e++)
            acc += Hs[ssrc[e]*Dc + t] * snorm[e];
        out[base + n*Dc + t] = siluf_(acc + b);
    }
}

// ---------------- aggregation + bias + SiLU + node-mean (fused final layer) ----------------
__global__ void __launch_bounds__(128) k_agg_mean(const float* __restrict__ Hin,
        const float* __restrict__ bias) {
    extern __shared__ float Hs[];
    __shared__ int   soff[Nn+1];
    __shared__ int   ssrc[Ec];
    __shared__ float snorm[Ec];
    __shared__ float sinvd[Nn];
    int t = threadIdx.x;
    int g = blockIdx.x;
    size_t base = (size_t)g * (Nn*Dc);
    for (int n = 0; n < Nn; n++) Hs[n*Dc + t] = Hin[base + n*Dc + t];
    for (int i = t; i <= Nn; i += 128) soff[i] = g_rowoff[i];
    for (int i = t; i < Ec; i += 128) { ssrc[i] = g_csrsrc[i]; snorm[i] = g_csrnorm[i]; }
    if (t < Nn) sinvd[t] = g_invdeg[t];
    __syncthreads();
    float b = bias[t];
    float macc = 0.f;
    for (int n = 0; n < Nn; n++) {
        float acc = Hs[n*Dc + t] * sinvd[n];
        int e0 = soff[n], e1 = soff[n+1];
        for (int e = e0; e < e1; e++)
            acc += Hs[ssrc[e]*Dc + t] * snorm[e];
        macc += siluf_(acc + b);
    }
    g_emb[g*Dc + t] = macc * (1.0f/(float)Nn);
}

// ---------------- fp32 GEMM: C[M,128] = A[M,128] @ W[128,128] ----------------
__global__ void __launch_bounds__(256,2) k_gemm(const float* __restrict__ A,
        const float* __restrict__ W, float* __restrict__ C) {
    __shared__ float As[16][132];   // transposed A tile, padded
    __shared__ float Ws[16][128];
    int tid = threadIdx.x;
    int tr = tid >> 4, tc = tid & 15;
    size_t bm = (size_t)blockIdx.x * 128;
    float acc[8][8];
    #pragma unroll
    for (int i = 0; i < 8; i++)
        #pragma unroll
        for (int j = 0; j < 8; j++) acc[i][j] = 0.f;

    for (int k0 = 0; k0 < 128; k0 += 16) {
        #pragma unroll
        for (int l = 0; l < 2; l++) {
            int idx = tid + l*256;
            int row = idx >> 2, c4 = idx & 3;
            float4 v = *(const float4*)(A + (bm+row)*128 + k0 + c4*4);
            As[c4*4+0][row] = v.x; As[c4*4+1][row] = v.y;
            As[c4*4+2][row] = v.z; As[c4*4+3][row] = v.w;
        }
        #pragma unroll
        for (int l = 0; l < 2; l++) {
            int idx = tid + l*256;
            int row = idx >> 5, c4 = idx & 31;
            *(float4*)(&Ws[row][c4*4]) = *(const float4*)(W + (k0+row)*128 + c4*4);
        }
        __syncthreads();
        #pragma unroll
        for (int k = 0; k < 16; k++) {
            float4 a0 = *(float4*)&As[k][tr*8];
            float4 a1 = *(float4*)&As[k][tr*8+4];
            float4 w0 = *(float4*)&Ws[k][tc*8];
            float4 w1 = *(float4*)&Ws[k][tc*8+4];
            float am[8] = {a0.x,a0.y,a0.z,a0.w,a1.x,a1.y,a1.z,a1.w};
            float wn[8] = {w0.x,w0.y,w0.z,w0.w,w1.x,w1.y,w1.z,w1.w};
            #pragma unroll
            for (int i = 0; i < 8; i++)
                #pragma unroll
                for (int j = 0; j < 8; j++)
                    acc[i][j] += am[i]*wn[j];
        }
        __syncthreads();
    }
    #pragma unroll
    for (int i = 0; i < 8; i++) {
        size_t r = bm + tr*8 + i;
        float4 o0 = make_float4(acc[i][0],acc[i][1],acc[i][2],acc[i][3]);
        float4 o1 = make_float4(acc[i][4],acc[i][5],acc[i][6],acc[i][7]);
        *(float4*)(C + r*128 + tc*8)     = o0;
        *(float4*)(C + r*128 + tc*8 + 4) = o1;
    }
}

// ---------------- xg0 = emb @ Wih0^T + bih0 + bhh0 (PERMUTED output layout) ----------------
__global__ void __launch_bounds__(512) k_xg0(const float* __restrict__ Wih0,
        const float* __restrict__ bih0, const float* __restrict__ bhh0) {
    __shared__ float es[16*128];
    int j = threadIdx.x;
    int m0 = blockIdx.x * 16;
    for (int i = j; i < 2048; i += 512) es[i] = g_emb[m0*128 + i];
    __syncthreads();
    const float4* wr = (const float4*)(Wih0 + (size_t)j*128);
    float acc[16];
    #pragma unroll
    for (int r = 0; r < 16; r++) acc[r] = 0.f;
    #pragma unroll 4
    for (int k4 = 0; k4 < 32; k4++) {
        float4 w = wr[k4];
        #pragma unroll
        for (int r = 0; r < 16; r++) {
            float4 e = *(const float4*)&es[r*128 + k4*4];
            acc[r] += w.x*e.x + w.y*e.y + w.z*e.z + w.w*e.w;
        }
    }
    float bb = bih0[j] + bhh0[j];
    int q = j >> 7, e = j & 127;
    int cr = e >> 5, l = e & 31;
    int pidx = cr*128 + q*32 + l;
    #pragma unroll
    for (int r = 0; r < 16; r++)
        g_xg0[(size_t)(m0+r)*512 + pidx] = acc[r] + bb;
}

// ---------------- LSTM v3: register-resident weights, pipelined layers, 1 handshake/step ----
// 4-CTA cluster per batch, 384 threads per CTA.
//  grp0 (t 0..127):   rows of Whh0  (layer0 recurrent gates)
//  grp1 (t 128..255): rows of Wih1  (layer1 input gates, + bias1 folded in)
//  grp2 (t 256..383): rows of Whh1  (layer1 recurrent gates)
// thread's row: gt=t&127, q=gt>>5, lane=gt&31, grow = q*128 + cta*32 + lane.
// Iteration s computes layer0 step s AND layer1 step s-1; one combined h exchange.
__global__ void __launch_bounds__(384,1) __cluster_dims__(CLN,1,1)
k_lstm3(const float* __restrict__ Whh0, const float* __restrict__ Wih1,
        const float* __restrict__ Whh1,
        const float* __restrict__ bih1, const float* __restrict__ bhh1) {
    __shared__ float h0buf[2][128];
    __shared__ float h1buf[2][128];
    __shared__ float sg[384];
    __shared__ __align__(8) unsigned long long mb;

    int t    = threadIdx.x;
    int grp  = t >> 7;           // 0,1,2
    int gt   = t & 127;
    int q    = gt >> 5;
    int lane = gt & 31;
    int cta  = blockIdx.x & (CLN-1);
    int b    = blockIdx.x / CLN;
    int grow = q*128 + cta*32 + lane;

    // load this thread's weight row into registers
    const float* Wsel = (grp == 0) ? Whh0 : (grp == 1) ? Wih1 : Whh1;
    float4 wreg[32];
    {
        const float4* gsrc = (const float4*)(Wsel + (size_t)grow*128);
        #pragma unroll
        for (int k = 0; k < 32; k++) wreg[k] = gsrc[k];
    }
    float bias1 = (grp == 1) ? (bih1[grow] + bhh1[grow]) : 0.f;

    if (t < 128) { h0buf[0][t] = 0.f; h0buf[1][t] = 0.f; h1buf[0][t] = 0.f; h1buf[1][t] = 0.f; }
    uint32_t mba = s2u(&mb);
    uint32_t h0a = s2u(h0buf), h1a = s2u(h1buf);
    if (t == 0)
        asm volatile("mbarrier.init.shared.b64 [%0], %1;" :: "r"(mba), "r"(256) : "memory");
    __syncthreads();
    asm volatile("barrier.cluster.arrive.aligned;" ::: "memory");
    asm volatile("barrier.cluster.wait.aligned;"   ::: "memory");

    float c0 = 0.f, c1 = 0.f;
    const float* xg = g_xg0 + (size_t)b*256*512 + cta*128 + gt;  // grp0 threads only

    for (int s = 0; s < 257; s++) {
        int p = s & 1;
        // ---- dot product against the right h buffer (broadcast smem reads) ----
        {
            const float4* hv = (grp == 2) ? (const float4*)h1buf[p] : (const float4*)h0buf[p];
            float4 a = make_float4(0,0,0,0), a2 = make_float4(0,0,0,0);
            #pragma unroll
            for (int k = 0; k < 32; k += 2) {
                float4 w = wreg[k],   h = hv[k];
                a.x += w.x*h.x; a.y += w.y*h.y; a.z += w.z*h.z; a.w += w.w*h.w;
                float4 w2 = wreg[k+1], h2 = hv[k+1];
                a2.x += w2.x*h2.x; a2.y += w2.y*h2.y; a2.z += w2.z*h2.z; a2.w += w2.w*h2.w;
            }
            float d = ((a.x+a.y)+(a.z+a.w)) + ((a2.x+a2.y)+(a2.z+a2.w));
            if (grp == 0) d += (s < 256) ? xg[(size_t)s*512] : 0.f;
            else if (grp == 1) d += bias1;
            sg[t] = d;
        }
        __syncthreads();
        bool last = (s == 256);
        if (t < 32 && !last) {
            // layer0 activation for element cta*32 + t, step s
            float gi = sg[t], gf = sg[32+t], gg = sg[64+t], go = sg[96+t];
            c0 = sigmoidf_(gf)*c0 + sigmoidf_(gi)*tanhf(gg);
            float hv0 = sigmoidf_(go)*tanhf(c0);
            uint32_t dst = h0a + (uint32_t)(((p^1)*128 + cta*32 + t)*4);
            #pragma unroll
            for (int peer = 0; peer < CLN; peer++) {
                st_cluster_f32(dst, peer, hv0);
                mbar_arrive_cluster(mba, peer);
            }
        }
        if (t >= 32 && t < 64) {
            // layer1 activation for element cta*32 + (t-32), step s-1
            int l = t - 32;
            float hv1;
            if (s == 0) {
                hv1 = 0.f;   // h1[-1] = 0
            } else {
                float gi = sg[128+l]      + sg[256+l];
                float gf = sg[128+32+l]   + sg[256+32+l];
                float gg = sg[128+64+l]   + sg[256+64+l];
                float go = sg[128+96+l]   + sg[256+96+l];
                c1 = sigmoidf_(gf)*c1 + sigmoidf_(gi)*tanhf(gg);
                hv1 = sigmoidf_(go)*tanhf(c1);
            }
            if (!last) {
                uint32_t dst = h1a + (uint32_t)(((p^1)*128 + cta*32 + l)*4);
                #pragma unroll
                for (int peer = 0; peer < CLN; peer++) {
                    st_cluster_f32(dst, peer, hv1);
                    mbar_arrive_cluster(mba, peer);
                }
            } else {
                g_final[b*128 + cta*32 + l] = hv1;   // h1[255]
            }
        }
        if (!last) mbar_wait_acq(mba, (uint32_t)p);
    }
}

// ---------------- head MLP ----------------
__global__ void __launch_bounds__(128) k_head(const float* __restrict__ hW1, const float* __restrict__ hb1,
        const float* __restrict__ hW2, const float* __restrict__ hb2,
        const float* __restrict__ hW3, const float* __restrict__ hb3,
        float* __restrict__ out) {
    __shared__ float sf[8*128], s1[8*128], s2[8*64];
    int t = threadIdx.x;
    for (int i = t; i < 1024; i += 128) sf[i] = g_final[i];
    __syncthreads();
    {
        int d = t;
        for (int b = 0; b < 8; b++) {
            float acc = hb1[d];
            for (int k = 0; k < 128; k++) acc += sf[b*128+k]*hW1[k*128+d];
            s1[b*128+d] = siluf_(acc);
        }
    }
    __syncthreads();
    if (t < 64) {
        int e = t;
        for (int b = 0; b < 8; b++) {
            float acc = hb2[e];
            for (int k = 0; k < 128; k++) acc += s1[b*128+k]*hW2[k*64+e];
            s2[b*64+e] = siluf_(acc);
        }
    }
    __syncthreads();
    if (t < 16) {
        int b = t >> 1, o = t & 1;
        float acc = hb3[o];
        for (int k = 0; k < 64; k++) acc += s2[b*64+k]*hW3[k*2+o];
        float sp = fmaxf(acc, 0.f) + log1pf(expf(-fabsf(acc)));
        out[b*2+o] = sp + 1e-6f;
    }
}

// ---------------- launch ----------------
extern "C" void kernel_launch(void* const* d_in, const int* in_sizes, int n_in,
                              void* d_out, int out_size) {
    const float* snap  = (const float*)d_in[0];
    const int*   ei    = (const int*)  d_in[1];
    const float* scale = (const float*)d_in[2];
    const float* shift = (const float*)d_in[3];
    const float* W1    = (const float*)d_in[4];
    const float* b1    = (const float*)d_in[5];
    const float* W2    = (const float*)d_in[6];
    const float* b2    = (const float*)d_in[7];
    const float* W3    = (const float*)d_in[8];
    const float* b3    = (const float*)d_in[9];
    const float* Wih0  = (const float*)d_in[10];
    const float* Whh0  = (const float*)d_in[11];
    const float* bih0  = (const float*)d_in[12];
    const float* bhh0  = (const float*)d_in[13];
    const float* Wih1  = (const float*)d_in[14];
    const float* Whh1  = (const float*)d_in[15];
    const float* bih1  = (const float*)d_in[16];
    const float* bhh1  = (const float*)d_in[17];
    const float* hW1   = (const float*)d_in[18];
    const float* hb1   = (const float*)d_in[19];
    const float* hW2   = (const float*)d_in[20];
    const float* hb2   = (const float*)d_in[21];
    const float* hW3   = (const float*)d_in[22];
    const float* hb3   = (const float*)d_in[23];
    float* out = (float*)d_out;

    float *H, *X;
    cudaGetSymbolAddress((void**)&H, g_H);
    cudaGetSymbolAddress((void**)&X, g_X);

    const int aggSmem = Nn*Dc*(int)sizeof(float);       // 60416
    cudaFuncSetAttribute(k_agg,      cudaFuncAttributeMaxDynamicSharedMemorySize, aggSmem);
    cudaFuncSetAttribute(k_agg_mean, cudaFuncAttributeMaxDynamicSharedMemorySize, aggSmem);
    cudaFuncSetAttribute(k_l1agg,    cudaFuncAttributeMaxDynamicSharedMemorySize, aggSmem);

    k_prep<<<1, 32>>>(ei);
    k_l1agg<<<Gc, 128, aggSmem>>>(snap, scale, shift, W1, b1, X);
    k_gemm<<<Mc/128, 256>>>(X, W2, H);
    k_agg<<<Gc, 128, aggSmem>>>(H, X, b2);
    k_gemm<<<Mc/128, 256>>>(X, W3, H);
    k_agg_mean<<<Gc, 128, aggSmem>>>(H, b3);
    k_xg0<<<Gc/16, 512>>>(Wih0, bih0, bhh0);
    k_lstm3<<<Bc*CLN, 384>>>(Whh0, Wih1, Whh1, bih1, bhh1);
    k_head<<<1, 128>>>(hW1, hb1, hW2, hb2, hW3, hb3, out);
}

// round 6
// speedup vs baseline: 6.1167x; 1.6761x over previous
#include <cuda_runtime.h>
#include <stdint.h>
#include <math.h>

#define Bc 8
#define Tc 256
#define Nn 118
#define Fc 3
#define Dc 128
#define Ec 372
#define Gc (Bc*Tc)          // 2048 graphs
#define Mc (Gc*Nn)          // 241664 rows
#define CLN 4               // cluster size for LSTM
#define HSTRIDE 132

// ---------------- scratch (device globals; no allocation allowed) ----------------
__device__ float g_X[(size_t)Mc*Dc];     // ~124MB ping
__device__ float g_Y[(size_t)Mc*Dc];     // ~124MB pong
__device__ float g_emb[Gc*Dc];
__device__ float g_xg0[(size_t)Gc*4*Dc]; // precomputed x@Wih0^T + biases (PERMUTED layout)
__device__ float g_final[Bc*Dc];
__device__ int   g_rowoff[Nn+1];
__device__ int   g_csrsrc[Ec];
__device__ float g_csrnorm[Ec];
__device__ float g_invdeg[Nn];

__device__ __forceinline__ float fsig(float x){ return __fdividef(1.0f, 1.0f + __expf(-x)); }
__device__ __forceinline__ float ftanh(float x){ return 2.0f*fsig(2.0f*x) - 1.0f; }
__device__ __forceinline__ float siluf_(float x){ return x*fsig(x); }

__device__ __forceinline__ uint32_t s2u(const void* p){
    uint32_t a;
    asm("{ .reg .u64 t; cvta.to.shared.u64 t, %1; cvt.u32.u64 %0, t; }" : "=r"(a) : "l"(p));
    return a;
}
// DSMEM store that completes tx-bytes on the destination CTA's mbarrier
__device__ __forceinline__ void st_async_f32(uint32_t laddr, uint32_t lmbar, uint32_t peer, float v){
    asm volatile("{ .reg .b32 ra, rb;\n\t"
                 "mapa.shared::cluster.u32 ra, %0, %2;\n\t"
                 "mapa.shared::cluster.u32 rb, %1, %2;\n\t"
                 "st.async.shared::cluster.mbarrier::complete_tx::bytes.b32 [ra], %3, [rb]; }"
                 :: "r"(laddr), "r"(lmbar), "r"(peer), "r"(__float_as_uint(v)) : "memory");
}
__device__ __forceinline__ void mbar_expect_tx(uint32_t mbar, uint32_t bytes){
    asm volatile("mbarrier.arrive.expect_tx.shared.b64 _, [%0], %1;"
                 :: "r"(mbar), "r"(bytes) : "memory");
}
__device__ __forceinline__ void mbar_wait(uint32_t addr, uint32_t parity){
    asm volatile("{\n\t"
        ".reg .pred P;\n\t"
        "WL%=:\n\t"
        "mbarrier.try_wait.parity.acquire.cluster.shared::cta.b64 P, [%0], %1, 0x989680;\n\t"
        "@!P bra WL%=;\n\t"
        "}" :: "r"(addr), "r"(parity) : "memory");
}

// ---------------- prep: decode edge_index (int32 or int64), build CSR ----------------
__global__ void k_prep(const int* __restrict__ ei) {
    if (threadIdx.x != 0) return;
    int ssrc[Ec], sdst[Ec];
    bool is64 = true;
    for (int i = 1; i < 2*Ec; i += 2) { if (ei[i] != 0) { is64 = false; break; } }
    for (int e = 0; e < Ec; e++) {
        if (is64) { ssrc[e] = ei[2*e]; sdst[e] = ei[2*(Ec+e)]; }
        else      { ssrc[e] = ei[e];   sdst[e] = ei[Ec+e];     }
    }
    float deg[Nn];
    for (int n = 0; n < Nn; n++) deg[n] = 1.0f;
    for (int e = 0; e < Ec; e++) deg[sdst[e]] += 1.0f;
    float inv[Nn];
    for (int n = 0; n < Nn; n++) {
        g_invdeg[n] = 1.0f/deg[n];
        inv[n] = 1.0f/sqrtf(deg[n]);
    }
    int cnt[Nn];
    for (int n = 0; n < Nn; n++) cnt[n] = 0;
    for (int e = 0; e < Ec; e++) cnt[sdst[e]]++;
    int off = 0;
    for (int n = 0; n < Nn; n++) { g_rowoff[n] = off; off += cnt[n]; cnt[n] = g_rowoff[n]; }
    g_rowoff[Nn] = off;
    for (int e = 0; e < Ec; e++) {
        int d = sdst[e]; int p = cnt[d]++;
        g_csrsrc[p]  = ssrc[e];
        g_csrnorm[p] = inv[ssrc[e]] * inv[d];
    }
}

// ---------------- fused layer1 GEMM (K=3) + aggregation + SiLU ----------------
__global__ void __launch_bounds__(256) k_l1agg(const float* __restrict__ snap,
        const float* __restrict__ scale, const float* __restrict__ shift,
        const float* __restrict__ W1, const float* __restrict__ bias,
        float* __restrict__ out) {
    extern __shared__ float Hs[];            // 118*HSTRIDE floats
    __shared__ float xs[Nn*Fc];
    __shared__ float sW[Fc*Dc];
    __shared__ int   soff[Nn+1];
    __shared__ int   ssrc[Ec];
    __shared__ float snorm[Ec];
    __shared__ float sinvd[Nn];
    int t = threadIdx.x;
    int g = blockIdx.x;
    for (int i = t; i < Nn*Fc; i += 256) {
        int f = i - (i/3)*3;
        xs[i] = snap[(size_t)g*Nn*Fc + i]*scale[f] + shift[f];
    }
    for (int i = t; i < Fc*Dc; i += 256) sW[i] = W1[i];
    for (int i = t; i <= Nn; i += 256) soff[i] = g_rowoff[i];
    for (int i = t; i < Ec; i += 256) { ssrc[i] = g_csrsrc[i]; snorm[i] = g_csrnorm[i]; }
    if (t < Nn) sinvd[t] = g_invdeg[t];
    __syncthreads();
    int c = t & 127, half = t >> 7;
    float w0 = sW[c], w1 = sW[128+c], w2 = sW[256+c];
    for (int n = half; n < Nn; n += 2)
        Hs[n*HSTRIDE + c] = xs[n*3]*w0 + xs[n*3+1]*w1 + xs[n*3+2]*w2;
    __syncthreads();
    float b = bias[c];
    size_t base = (size_t)g * (Nn*Dc);
    for (int n = half; n < Nn; n += 2) {
        float acc = Hs[n*HSTRIDE + c] * sinvd[n];
        int e0 = soff[n], e1 = soff[n+1];
        for (int e = e0; e < e1; e++)
            acc += Hs[ssrc[e]*HSTRIDE + c] * snorm[e];
        out[base + n*Dc + c] = siluf_(acc + b);
    }
}

// ---------------- fused GEMM(128x128) + aggregation + SiLU (+optional mean) ----------------
// One graph per 256-thread block. GEMM uses k_gemm's register tiling, result kept in smem.
template<bool DOMEAN>
__global__ void __launch_bounds__(256,2) k_fused(const float* __restrict__ A,
        const float* __restrict__ W, const float* __restrict__ bias,
        float* __restrict__ out) {
    extern __shared__ float dyn[];
    float* As = dyn;                    // [16][132]
    float* Ws = As + 16*132;            // [16][128]
    float* Hs = Ws + 16*128;            // [118][HSTRIDE]
    __shared__ int   soff[Nn+1];
    __shared__ int   ssrc[Ec];
    __shared__ float snorm[Ec];
    __shared__ float sinvd[Nn];
    __shared__ float sred[256];

    int tid = threadIdx.x;
    int g = blockIdx.x;
    const float* Ag = A + (size_t)g*Nn*Dc;

    for (int i = tid; i <= Nn; i += 256) soff[i] = g_rowoff[i];
    for (int i = tid; i < Ec; i += 256) { ssrc[i] = g_csrsrc[i]; snorm[i] = g_csrnorm[i]; }
    if (tid < Nn) sinvd[tid] = g_invdeg[tid];

    int tr = tid >> 4, tc = tid & 15;
    float acc[8][8];
    #pragma unroll
    for (int i = 0; i < 8; i++)
        #pragma unroll
        for (int j = 0; j < 8; j++) acc[i][j] = 0.f;

    for (int k0 = 0; k0 < 128; k0 += 16) {
        #pragma unroll
        for (int l = 0; l < 2; l++) {
            int idx = tid + l*256;
            int row = idx >> 2, c4 = idx & 3;
            int arow = (row < Nn) ? row : (Nn-1);
            float4 v = *(const float4*)(Ag + arow*Dc + k0 + c4*4);
            As[(c4*4+0)*132+row] = v.x; As[(c4*4+1)*132+row] = v.y;
            As[(c4*4+2)*132+row] = v.z; As[(c4*4+3)*132+row] = v.w;
        }
        #pragma unroll
        for (int l = 0; l < 2; l++) {
            int idx = tid + l*256;
            int row = idx >> 5, c4 = idx & 31;
            *(float4*)(&Ws[row*128 + c4*4]) = *(const float4*)(W + (k0+row)*128 + c4*4);
        }
        __syncthreads();
        #pragma unroll
        for (int k = 0; k < 16; k++) {
            float4 a0 = *(float4*)&As[k*132 + tr*8];
            float4 a1 = *(float4*)&As[k*132 + tr*8+4];
            float4 w0 = *(float4*)&Ws[k*128 + tc*8];
            float4 w1 = *(float4*)&Ws[k*128 + tc*8+4];
            float am[8] = {a0.x,a0.y,a0.z,a0.w,a1.x,a1.y,a1.z,a1.w};
            float wn[8] = {w0.x,w0.y,w0.z,w0.w,w1.x,w1.y,w1.z,w1.w};
            #pragma unroll
            for (int i = 0; i < 8; i++)
                #pragma unroll
                for (int j = 0; j < 8; j++)
                    acc[i][j] += am[i]*wn[j];
        }
        __syncthreads();
    }
    #pragma unroll
    for (int i = 0; i < 8; i++) {
        int r = tr*8 + i;
        if (r < Nn) {
            *(float4*)(Hs + r*HSTRIDE + tc*8)     = make_float4(acc[i][0],acc[i][1],acc[i][2],acc[i][3]);
            *(float4*)(Hs + r*HSTRIDE + tc*8 + 4) = make_float4(acc[i][4],acc[i][5],acc[i][6],acc[i][7]);
        }
    }
    __syncthreads();

    int c = tid & 127, half = tid >> 7;
    float b = bias[c];
    size_t base = (size_t)g * (Nn*Dc);
    float macc = 0.f;
    for (int n = half; n < Nn; n += 2) {
        float a = Hs[n*HSTRIDE + c] * sinvd[n];
        int e0 = soff[n], e1 = soff[n+1];
        for (int e = e0; e < e1; e++)
            a += Hs[ssrc[e]*HSTRIDE + c] * snorm[e];
        float v = siluf_(a + b);
        if (DOMEAN) macc += v;
        else        out[base + n*Dc + c] = v;
    }
    if (DOMEAN) {
        sred[tid] = macc;
        __syncthreads();
        if (tid < 128)
            g_emb[g*Dc + tid] = (sred[tid] + sred[128+tid]) * (1.0f/(float)Nn);
    }
}

// ---------------- xg0 = emb @ Wih0^T + bih0 + bhh0 (PERMUTED output layout) ----------------
__global__ void __launch_bounds__(512) k_xg0(const float* __restrict__ Wih0,
        const float* __restrict__ bih0, const float* __restrict__ bhh0) {
    __shared__ float es[16*128];
    int j = threadIdx.x;
    int m0 = blockIdx.x * 16;
    for (int i = j; i < 2048; i += 512) es[i] = g_emb[m0*128 + i];
    __syncthreads();
    const float4* wr = (const float4*)(Wih0 + (size_t)j*128);
    float acc[16];
    #pragma unroll
    for (int r = 0; r < 16; r++) acc[r] = 0.f;
    #pragma unroll 4
    for (int k4 = 0; k4 < 32; k4++) {
        float4 w = wr[k4];
        #pragma unroll
        for (int r = 0; r < 16; r++) {
            float4 e = *(const float4*)&es[r*128 + k4*4];
            acc[r] += w.x*e.x + w.y*e.y + w.z*e.z + w.w*e.w;
        }
    }
    float bb = bih0[j] + bhh0[j];
    int q = j >> 7, e = j & 127;
    int cr = e >> 5, l = e & 31;
    int pidx = cr*128 + q*32 + l;
    #pragma unroll
    for (int r = 0; r < 16; r++)
        g_xg0[(size_t)(m0+r)*512 + pidx] = acc[r] + bb;
}

// ---------------- LSTM v4: register weights, pipelined layers, st.async handshake ----------
// 4-CTA cluster per batch, 384 threads per CTA.
//  grp0 (t 0..127):   rows of Whh0   grp1: Wih1 (+bias1)   grp2: Whh1
// Iteration s computes layer0 step s AND layer1 step s-1; combined h exchange via
// st.async with mbarrier::complete_tx onto ping-pong mbars (1024 B expected per step).
__global__ void __launch_bounds__(384,1) __cluster_dims__(CLN,1,1)
k_lstm4(const float* __restrict__ Whh0, const float* __restrict__ Wih1,
        const float* __restrict__ Whh1,
        const float* __restrict__ bih1, const float* __restrict__ bhh1) {
    __shared__ float h0buf[2][128];
    __shared__ float h1buf[2][128];
    __shared__ float sg[384];
    __shared__ __align__(8) unsigned long long mbs[2];

    int t    = threadIdx.x;
    int grp  = t >> 7;           // 0,1,2
    int gt   = t & 127;
    int q    = gt >> 5;
    int lane = gt & 31;
    int cta  = blockIdx.x & (CLN-1);
    int b    = blockIdx.x / CLN;
    int grow = q*128 + cta*32 + lane;

    const float* Wsel = (grp == 0) ? Whh0 : (grp == 1) ? Wih1 : Whh1;
    float4 wreg[32];
    {
        const float4* gsrc = (const float4*)(Wsel + (size_t)grow*128);
        #pragma unroll
        for (int k = 0; k < 32; k++) wreg[k] = gsrc[k];
    }
    float bias1 = (grp == 1) ? (bih1[grow] + bhh1[grow]) : 0.f;

    if (t < 128) { h0buf[0][t] = 0.f; h0buf[1][t] = 0.f; h1buf[0][t] = 0.f; h1buf[1][t] = 0.f; }
    uint32_t mba0 = s2u(&mbs[0]), mba1 = s2u(&mbs[1]);
    uint32_t h0a = s2u(h0buf), h1a = s2u(h1buf);
    if (t == 0) {
        asm volatile("mbarrier.init.shared.b64 [%0], %1;" :: "r"(mba0), "r"(1) : "memory");
        asm volatile("mbarrier.init.shared.b64 [%0], %1;" :: "r"(mba1), "r"(1) : "memory");
    }
    __syncthreads();
    asm volatile("barrier.cluster.arrive.aligned;" ::: "memory");
    asm volatile("barrier.cluster.wait.aligned;"   ::: "memory");

    float c0 = 0.f, c1 = 0.f;
    const float* xg = g_xg0 + (size_t)b*256*512 + cta*128 + gt;  // grp0 threads only

    for (int s = 0; s < 257; s++) {
        int p = s & 1;
        bool last = (s == 256);
        uint32_t mba = (s & 1) ? mba1 : mba0;
        uint32_t parity = (uint32_t)((s >> 1) & 1);
        if (t == 0 && !last) mbar_expect_tx(mba, 1024u);
        float xv = (grp == 0 && !last) ? xg[(size_t)s*512] : 0.f;
        // ---- dot product against the right h buffer (broadcast smem reads) ----
        {
            const float4* hv = (grp == 2) ? (const float4*)h1buf[p] : (const float4*)h0buf[p];
            float4 a = make_float4(0,0,0,0), a2 = make_float4(0,0,0,0);
            #pragma unroll
            for (int k = 0; k < 32; k += 2) {
                float4 w = wreg[k],   h = hv[k];
                a.x += w.x*h.x; a.y += w.y*h.y; a.z += w.z*h.z; a.w += w.w*h.w;
                float4 w2 = wreg[k+1], h2 = hv[k+1];
                a2.x += w2.x*h2.x; a2.y += w2.y*h2.y; a2.z += w2.z*h2.z; a2.w += w2.w*h2.w;
            }
            float d = ((a.x+a.y)+(a.z+a.w)) + ((a2.x+a2.y)+(a2.z+a2.w));
            if (grp == 0) d += xv;
            else if (grp == 1) d += bias1;
            sg[t] = d;
        }
        __syncthreads();
        if (t < 32 && !last) {
            float gi = sg[t], gf = sg[32+t], gg = sg[64+t], go = sg[96+t];
            c0 = fsig(gf)*c0 + fsig(gi)*ftanh(gg);
            float hv0 = fsig(go)*ftanh(c0);
            uint32_t dst = h0a + (uint32_t)(((p^1)*128 + cta*32 + t)*4);
            #pragma unroll
            for (int peer = 0; peer < CLN; peer++)
                st_async_f32(dst, mba, (uint32_t)peer, hv0);
        }
        if (t >= 32 && t < 64) {
            int l = t - 32;
            float hv1;
            if (s == 0) {
                hv1 = 0.f;   // h1[-1] = 0
            } else {
                float gi = sg[128+l]      + sg[256+l];
                float gf = sg[128+32+l]   + sg[256+32+l];
                float gg = sg[128+64+l]   + sg[256+64+l];
                float go = sg[128+96+l]   + sg[256+96+l];
                c1 = fsig(gf)*c1 + fsig(gi)*ftanh(gg);
                hv1 = fsig(go)*ftanh(c1);
            }
            if (!last) {
                uint32_t dst = h1a + (uint32_t)(((p^1)*128 + cta*32 + l)*4);
                #pragma unroll
                for (int peer = 0; peer < CLN; peer++)
                    st_async_f32(dst, mba, (uint32_t)peer, hv1);
            } else {
                g_final[b*128 + cta*32 + l] = hv1;   // h1[255]
            }
        }
        if (!last) mbar_wait(mba, parity);
    }
}

// ---------------- head MLP ----------------
__global__ void __launch_bounds__(128) k_head(const float* __restrict__ hW1, const float* __restrict__ hb1,
        const float* __restrict__ hW2, const float* __restrict__ hb2,
        const float* __restrict__ hW3, const float* __restrict__ hb3,
        float* __restrict__ out) {
    __shared__ float sf[8*128], s1[8*128], s2[8*64];
    int t = threadIdx.x;
    for (int i = t; i < 1024; i += 128) sf[i] = g_final[i];
    __syncthreads();
    {
        int d = t;
        for (int b = 0; b < 8; b++) {
            float acc = hb1[d];
            for (int k = 0; k < 128; k++) acc += sf[b*128+k]*hW1[k*128+d];
            s1[b*128+d] = siluf_(acc);
        }
    }
    __syncthreads();
    if (t < 64) {
        int e = t;
        for (int b = 0; b < 8; b++) {
            float acc = hb2[e];
            for (int k = 0; k < 128; k++) acc += s1[b*128+k]*hW2[k*64+e];
            s2[b*64+e] = siluf_(acc);
        }
    }
    __syncthreads();
    if (t < 16) {
        int b = t >> 1, o = t & 1;
        float acc = hb3[o];
        for (int k = 0; k < 64; k++) acc += s2[b*64+k]*hW3[k*2+o];
        float sp = fmaxf(acc, 0.f) + log1pf(expf(-fabsf(acc)));
        out[b*2+o] = sp + 1e-6f;
    }
}

// ---------------- launch ----------------
extern "C" void kernel_launch(void* const* d_in, const int* in_sizes, int n_in,
                              void* d_out, int out_size) {
    const float* snap  = (const float*)d_in[0];
    const int*   ei    = (const int*)  d_in[1];
    const float* scale = (const float*)d_in[2];
    const float* shift = (const float*)d_in[3];
    const float* W1    = (const float*)d_in[4];
    const float* b1    = (const float*)d_in[5];
    const float* W2    = (const float*)d_in[6];
    const float* b2    = (const float*)d_in[7];
    const float* W3    = (const float*)d_in[8];
    const float* b3    = (const float*)d_in[9];
    const float* Wih0  = (const float*)d_in[10];
    const float* Whh0  = (const float*)d_in[11];
    const float* bih0  = (const float*)d_in[12];
    const float* bhh0  = (const float*)d_in[13];
    const float* Wih1  = (const float*)d_in[14];
    const float* Whh1  = (const float*)d_in[15];
    const float* bih1  = (const float*)d_in[16];
    const float* bhh1  = (const float*)d_in[17];
    const float* hW1   = (const float*)d_in[18];
    const float* hb1   = (const float*)d_in[19];
    const float* hW2   = (const float*)d_in[20];
    const float* hb2   = (const float*)d_in[21];
    const float* hW3   = (const float*)d_in[22];
    const float* hb3   = (const float*)d_in[23];
    float* out = (float*)d_out;

    float *X, *Y;
    cudaGetSymbolAddress((void**)&X, g_X);
    cudaGetSymbolAddress((void**)&Y, g_Y);

    const int l1Smem    = Nn*HSTRIDE*(int)sizeof(float);                  // 62304
    const int fusedSmem = (16*132 + 16*128 + Nn*HSTRIDE)*(int)sizeof(float); // 78944
    cudaFuncSetAttribute(k_l1agg,          cudaFuncAttributeMaxDynamicSharedMemorySize, l1Smem);
    cudaFuncSetAttribute(k_fused<false>,   cudaFuncAttributeMaxDynamicSharedMemorySize, fusedSmem);
    cudaFuncSetAttribute(k_fused<true>,    cudaFuncAttributeMaxDynamicSharedMemorySize, fusedSmem);

    k_prep<<<1, 32>>>(ei);
    k_l1agg<<<Gc, 256, l1Smem>>>(snap, scale, shift, W1, b1, X);
    k_fused<false><<<Gc, 256, fusedSmem>>>(X, W2, b2, Y);
    k_fused<true ><<<Gc, 256, fusedSmem>>>(Y, W3, b3, nullptr);
    k_xg0<<<Gc/16, 512>>>(Wih0, bih0, bhh0);
    k_lstm4<<<Bc*CLN, 384>>>(Whh0, Wih1, Whh1, bih1, bhh1);
    k_head<<<1, 128>>>(hW1, hb1, hW2, hb2, hW3, hb3, out);
}

// round 7
// speedup vs baseline: 7.5890x; 1.2407x over previous
#include <cuda_runtime.h>
#include <stdint.h>
#include <math.h>

#define Bc 8
#define Tc 256
#define Nn 118
#define Fc 3
#define Dc 128
#define Ec 372
#define Gc (Bc*Tc)          // 2048 graphs
#define Mc (Gc*Nn)          // 241664 rows
#define CLN 4               // cluster size for LSTM
#define HST 132             // Hs/Hg row stride (floats)
#define WST 136             // W row stride (floats)

// ---------------- scratch (device globals; no allocation allowed) ----------------
__device__ float g_emb[Gc*Dc];
__device__ float g_xg0[(size_t)Gc*4*Dc]; // precomputed x@Wih0^T + biases (PERMUTED layout)
__device__ float g_final[Bc*Dc];
__device__ int   g_rowoff[Nn+1];
__device__ int   g_csrsrc[Ec];
__device__ float g_csrnorm[Ec];
__device__ float g_invdeg[Nn];

__device__ __forceinline__ float fsig(float x){ return __fdividef(1.0f, 1.0f + __expf(-x)); }
__device__ __forceinline__ float ftanh(float x){ return 2.0f*fsig(2.0f*x) - 1.0f; }
__device__ __forceinline__ float siluf_(float x){ return x*fsig(x); }
__device__ __forceinline__ float tf32f(float x){
    uint32_t u; asm("cvt.rna.tf32.f32 %0, %1;" : "=r"(u) : "f"(x));
    return __uint_as_float(u);
}

__device__ __forceinline__ uint32_t s2u(const void* p){
    uint32_t a;
    asm("{ .reg .u64 t; cvta.to.shared.u64 t, %1; cvt.u32.u64 %0, t; }" : "=r"(a) : "l"(p));
    return a;
}
__device__ __forceinline__ void st_async_f32(uint32_t laddr, uint32_t lmbar, uint32_t peer, float v){
    asm volatile("{ .reg .b32 ra, rb;\n\t"
                 "mapa.shared::cluster.u32 ra, %0, %2;\n\t"
                 "mapa.shared::cluster.u32 rb, %1, %2;\n\t"
                 "st.async.shared::cluster.mbarrier::complete_tx::bytes.b32 [ra], %3, [rb]; }"
                 :: "r"(laddr), "r"(lmbar), "r"(peer), "r"(__float_as_uint(v)) : "memory");
}
__device__ __forceinline__ void mbar_expect_tx(uint32_t mbar, uint32_t bytes){
    asm volatile("mbarrier.arrive.expect_tx.shared.b64 _, [%0], %1;"
                 :: "r"(mbar), "r"(bytes) : "memory");
}
__device__ __forceinline__ void mbar_wait(uint32_t addr, uint32_t parity){
    asm volatile("{\n\t"
        ".reg .pred P;\n\t"
        "WL%=:\n\t"
        "mbarrier.try_wait.parity.acquire.cluster.shared::cta.b64 P, [%0], %1, 0x989680;\n\t"
        "@!P bra WL%=;\n\t"
        "}" :: "r"(addr), "r"(parity) : "memory");
}

// ---------------- prep: decode edge_index (int32 or int64), build CSR ----------------
__global__ void k_prep(const int* __restrict__ ei) {
    if (threadIdx.x != 0) return;
    int ssrc[Ec], sdst[Ec];
    bool is64 = true;
    for (int i = 1; i < 2*Ec; i += 2) { if (ei[i] != 0) { is64 = false; break; } }
    for (int e = 0; e < Ec; e++) {
        if (is64) { ssrc[e] = ei[2*e]; sdst[e] = ei[2*(Ec+e)]; }
        else      { ssrc[e] = ei[e];   sdst[e] = ei[Ec+e];     }
    }
    float deg[Nn];
    for (int n = 0; n < Nn; n++) deg[n] = 1.0f;
    for (int e = 0; e < Ec; e++) deg[sdst[e]] += 1.0f;
    float inv[Nn];
    for (int n = 0; n < Nn; n++) {
        g_invdeg[n] = 1.0f/deg[n];
        inv[n] = 1.0f/sqrtf(deg[n]);
    }
    int cnt[Nn];
    for (int n = 0; n < Nn; n++) cnt[n] = 0;
    for (int e = 0; e < Ec; e++) cnt[sdst[e]]++;
    int off = 0;
    for (int n = 0; n < Nn; n++) { g_rowoff[n] = off; off += cnt[n]; cnt[n] = g_rowoff[n]; }
    g_rowoff[Nn] = off;
    for (int e = 0; e < Ec; e++) {
        int d = sdst[e]; int p = cnt[d]++;
        g_csrsrc[p]  = ssrc[e];
        g_csrnorm[p] = inv[ssrc[e]] * inv[d];
    }
}

// ---------------- mega: whole GCN stack per graph in one block ----------------
// dyn smem: Hg[128*HST] (fp32 GEMM out) | Hs[128*HST] (tf32 GEMM in) | Ws[128*WST] (tf32 W)
__global__ void __launch_bounds__(512,1) k_mega(const float* __restrict__ snap,
        const float* __restrict__ scale, const float* __restrict__ shift,
        const float* __restrict__ W1, const float* __restrict__ b1,
        const float* __restrict__ W2, const float* __restrict__ b2,
        const float* __restrict__ W3, const float* __restrict__ b3) {
    extern __shared__ float dyn[];
    float* Hg = dyn;
    float* Hs = Hg + 128*HST;
    float* Ws = Hs + 128*HST;
    __shared__ int   soff[Nn+1];
    __shared__ int   ssrc[Ec];
    __shared__ float snorm[Ec];
    __shared__ float sinvd[Nn];
    __shared__ float xs[Nn*Fc];
    __shared__ float sW1[Fc*Dc];
    __shared__ float sred[512];

    int t = threadIdx.x;
    int g = blockIdx.x;
    int c = t & 127, qr = t >> 7;

    for (int i = t; i < Nn*Fc; i += 512) {
        int f = i - (i/3)*3;
        xs[i] = snap[(size_t)g*Nn*Fc + i]*scale[f] + shift[f];
    }
    for (int i = t; i < Fc*Dc; i += 512) sW1[i] = W1[i];
    for (int i = t; i <= Nn; i += 512) soff[i] = g_rowoff[i];
    for (int i = t; i < Ec; i += 512) { ssrc[i] = g_csrsrc[i]; snorm[i] = g_csrnorm[i]; }
    if (t < Nn) sinvd[t] = g_invdeg[t];
    // W2 -> Ws (tf32)
    for (int i = t; i < 128*128; i += 512) {
        int k = i >> 7, n = i & 127;
        Ws[k*WST + n] = tf32f(W2[i]);
    }
    // zero Hs pad rows (118..127)
    for (int i = t; i < 10*128; i += 512) {
        int r = i >> 7, cc = i & 127;
        Hs[(Nn + r)*HST + cc] = 0.f;
    }
    __syncthreads();

    // GEMM1 (K=3, fp32)
    for (int i = t; i < Nn*128; i += 512) {
        int n = i >> 7, cc = i & 127;
        Hg[n*HST + cc] = fmaf(xs[n*3], sW1[cc],
                         fmaf(xs[n*3+1], sW1[128+cc], xs[n*3+2]*sW1[256+cc]));
    }
    __syncthreads();

    // agg1: Hg -> Hs (silu, tf32)
    {
        float b = b1[c];
        for (int n = qr; n < Nn; n += 4) {
            float a = Hg[n*HST + c] * sinvd[n];
            int e0 = soff[n], e1 = soff[n+1];
            for (int e = e0; e < e1; e++) a += Hg[ssrc[e]*HST + c] * snorm[e];
            Hs[n*HST + c] = tf32f(siluf_(a + b));
        }
    }
    __syncthreads();

    // tf32 mma GEMM macro-ish lambda: Hg = Hs @ Ws
    int wid = t >> 5, lane = t & 31;
    int mbase = (wid & 7) * 16, nhalf = (wid >> 3) * 64;
    int gq = lane >> 2, tig = lane & 3;

    #define DO_GEMM() do { \
        float acc[8][4]; \
        _Pragma("unroll") \
        for (int j = 0; j < 8; j++) { acc[j][0]=0.f; acc[j][1]=0.f; acc[j][2]=0.f; acc[j][3]=0.f; } \
        const float* Ar0 = Hs + (mbase+gq)*HST; \
        const float* Ar1 = Hs + (mbase+gq+8)*HST; \
        for (int k0 = 0; k0 < 128; k0 += 8) { \
            uint32_t a0 = __float_as_uint(Ar0[k0+tig]); \
            uint32_t a1 = __float_as_uint(Ar1[k0+tig]); \
            uint32_t a2 = __float_as_uint(Ar0[k0+tig+4]); \
            uint32_t a3 = __float_as_uint(Ar1[k0+tig+4]); \
            const float* B0 = Ws + (k0+tig)*WST + nhalf + gq; \
            const float* B1 = Ws + (k0+tig+4)*WST + nhalf + gq; \
            _Pragma("unroll") \
            for (int j = 0; j < 8; j++) { \
                uint32_t b0 = __float_as_uint(B0[8*j]); \
                uint32_t b1_ = __float_as_uint(B1[8*j]); \
                asm volatile("mma.sync.aligned.m16n8k8.row.col.f32.tf32.tf32.f32 " \
                    "{%0,%1,%2,%3}, {%4,%5,%6,%7}, {%8,%9}, {%0,%1,%2,%3};" \
                    : "+f"(acc[j][0]), "+f"(acc[j][1]), "+f"(acc[j][2]), "+f"(acc[j][3]) \
                    : "r"(a0), "r"(a1), "r"(a2), "r"(a3), "r"(b0), "r"(b1_)); \
            } \
        } \
        _Pragma("unroll") \
        for (int j = 0; j < 8; j++) { \
            float* o0 = Hg + (mbase+gq)*HST   + nhalf + 8*j + 2*tig; \
            float* o1 = Hg + (mbase+gq+8)*HST + nhalf + 8*j + 2*tig; \
            o0[0] = acc[j][0]; o0[1] = acc[j][1]; \
            o1[0] = acc[j][2]; o1[1] = acc[j][3]; \
        } \
    } while(0)

    DO_GEMM();           // GEMM2
    __syncthreads();

    // agg2: Hg -> Hs ; concurrently reload W3 -> Ws
    {
        float b = b2[c];
        for (int n = qr; n < Nn; n += 4) {
            float a = Hg[n*HST + c] * sinvd[n];
            int e0 = soff[n], e1 = soff[n+1];
            for (int e = e0; e < e1; e++) a += Hg[ssrc[e]*HST + c] * snorm[e];
            Hs[n*HST + c] = tf32f(siluf_(a + b));
        }
        for (int i = t; i < 128*128; i += 512) {
            int k = i >> 7, n = i & 127;
            Ws[k*WST + n] = tf32f(W3[i]);
        }
    }
    __syncthreads();

    DO_GEMM();           // GEMM3
    __syncthreads();

    // agg3 + silu + mean
    {
        float b = b3[c];
        float macc = 0.f;
        for (int n = qr; n < Nn; n += 4) {
            float a = Hg[n*HST + c] * sinvd[n];
            int e0 = soff[n], e1 = soff[n+1];
            for (int e = e0; e < e1; e++) a += Hg[ssrc[e]*HST + c] * snorm[e];
            macc += siluf_(a + b);
        }
        sred[t] = macc;
        __syncthreads();
        if (t < 128)
            g_emb[g*Dc + t] = (sred[t] + sred[128+t] + sred[256+t] + sred[384+t]) * (1.0f/(float)Nn);
    }
    #undef DO_GEMM
}

// ---------------- xg0 = emb @ Wih0^T + bih0 + bhh0 (PERMUTED output layout) ----------------
__global__ void __launch_bounds__(512) k_xg0(const float* __restrict__ Wih0,
        const float* __restrict__ bih0, const float* __restrict__ bhh0) {
    __shared__ float es[16*128];
    int j = threadIdx.x;
    int m0 = blockIdx.x * 16;
    for (int i = j; i < 2048; i += 512) es[i] = g_emb[m0*128 + i];
    __syncthreads();
    const float4* wr = (const float4*)(Wih0 + (size_t)j*128);
    float acc[16];
    #pragma unroll
    for (int r = 0; r < 16; r++) acc[r] = 0.f;
    #pragma unroll 4
    for (int k4 = 0; k4 < 32; k4++) {
        float4 w = wr[k4];
        #pragma unroll
        for (int r = 0; r < 16; r++) {
            float4 e = *(const float4*)&es[r*128 + k4*4];
            acc[r] += w.x*e.x + w.y*e.y + w.z*e.z + w.w*e.w;
        }
    }
    float bb = bih0[j] + bhh0[j];
    int q = j >> 7, e = j & 127;
    int cr = e >> 5, l = e & 31;
    int pidx = cr*128 + q*32 + l;
    #pragma unroll
    for (int r = 0; r < 16; r++)
        g_xg0[(size_t)(m0+r)*512 + pidx] = acc[r] + bb;
}

// ---------------- LSTM v4: register weights, pipelined layers, st.async handshake ----------
__global__ void __launch_bounds__(384,1) __cluster_dims__(CLN,1,1)
k_lstm4(const float* __restrict__ Whh0, const float* __restrict__ Wih1,
        const float* __restrict__ Whh1,
        const float* __restrict__ bih1, const float* __restrict__ bhh1) {
    __shared__ float h0buf[2][128];
    __shared__ float h1buf[2][128];
    __shared__ float sg[384];
    __shared__ __align__(8) unsigned long long mbs[2];

    int t    = threadIdx.x;
    int grp  = t >> 7;           // 0,1,2
    int gt   = t & 127;
    int q    = gt >> 5;
    int lane = gt & 31;
    int cta  = blockIdx.x & (CLN-1);
    int b    = blockIdx.x / CLN;
    int grow = q*128 + cta*32 + lane;

    const float* Wsel = (grp == 0) ? Whh0 : (grp == 1) ? Wih1 : Whh1;
    float4 wreg[32];
    {
        const float4* gsrc = (const float4*)(Wsel + (size_t)grow*128);
        #pragma unroll
        for (int k = 0; k < 32; k++) wreg[k] = gsrc[k];
    }
    float bias1 = (grp == 1) ? (bih1[grow] + bhh1[grow]) : 0.f;

    if (t < 128) { h0buf[0][t] = 0.f; h0buf[1][t] = 0.f; h1buf[0][t] = 0.f; h1buf[1][t] = 0.f; }
    uint32_t mba0 = s2u(&mbs[0]), mba1 = s2u(&mbs[1]);
    uint32_t h0a = s2u(h0buf), h1a = s2u(h1buf);
    if (t == 0) {
        asm volatile("mbarrier.init.shared.b64 [%0], %1;" :: "r"(mba0), "r"(1) : "memory");
        asm volatile("mbarrier.init.shared.b64 [%0], %1;" :: "r"(mba1), "r"(1) : "memory");
    }
    __syncthreads();
    asm volatile("barrier.cluster.arrive.aligned;" ::: "memory");
    asm volatile("barrier.cluster.wait.aligned;"   ::: "memory");

    float c0 = 0.f, c1 = 0.f;
    const float* xg = g_xg0 + (size_t)b*256*512 + cta*128 + gt;  // grp0 threads only

    for (int s = 0; s < 257; s++) {
        int p = s & 1;
        bool last = (s == 256);
        uint32_t mba = (s & 1) ? mba1 : mba0;
        uint32_t parity = (uint32_t)((s >> 1) & 1);
        if (t == 0 && !last) mbar_expect_tx(mba, 1024u);
        float xv = (grp == 0 && !last) ? xg[(size_t)s*512] : 0.f;
        {
            const float4* hv = (grp == 2) ? (const float4*)h1buf[p] : (const float4*)h0buf[p];
            float4 a = make_float4(0,0,0,0), a2 = make_float4(0,0,0,0);
            #pragma unroll
            for (int k = 0; k < 32; k += 2) {
                float4 w = wreg[k],   h = hv[k];
                a.x += w.x*h.x; a.y += w.y*h.y; a.z += w.z*h.z; a.w += w.w*h.w;
                float4 w2 = wreg[k+1], h2 = hv[k+1];
                a2.x += w2.x*h2.x; a2.y += w2.y*h2.y; a2.z += w2.z*h2.z; a2.w += w2.w*h2.w;
            }
            float d = ((a.x+a.y)+(a.z+a.w)) + ((a2.x+a2.y)+(a2.z+a2.w));
            if (grp == 0) d += xv;
            else if (grp == 1) d += bias1;
            sg[t] = d;
        }
        __syncthreads();
        if (t < 32 && !last) {
            float gi = sg[t], gf = sg[32+t], gg = sg[64+t], go = sg[96+t];
            c0 = fsig(gf)*c0 + fsig(gi)*ftanh(gg);
            float hv0 = fsig(go)*ftanh(c0);
            uint32_t dst = h0a + (uint32_t)(((p^1)*128 + cta*32 + t)*4);
            #pragma unroll
            for (int peer = 0; peer < CLN; peer++)
                st_async_f32(dst, mba, (uint32_t)peer, hv0);
        }
        if (t >= 32 && t < 64) {
            int l = t - 32;
            float hv1;
            if (s == 0) {
                hv1 = 0.f;
            } else {
                float gi = sg[128+l]      + sg[256+l];
                float gf = sg[128+32+l]   + sg[256+32+l];
                float gg = sg[128+64+l]   + sg[256+64+l];
                float go = sg[128+96+l]   + sg[256+96+l];
                c1 = fsig(gf)*c1 + fsig(gi)*ftanh(gg);
                hv1 = fsig(go)*ftanh(c1);
            }
            if (!last) {
                uint32_t dst = h1a + (uint32_t)(((p^1)*128 + cta*32 + l)*4);
                #pragma unroll
                for (int peer = 0; peer < CLN; peer++)
                    st_async_f32(dst, mba, (uint32_t)peer, hv1);
            } else {
                g_final[b*128 + cta*32 + l] = hv1;
            }
        }
        if (!last) mbar_wait(mba, parity);
    }
}

// ---------------- head MLP ----------------
__global__ void __launch_bounds__(128) k_head(const float* __restrict__ hW1, const float* __restrict__ hb1,
        const float* __restrict__ hW2, const float* __restrict__ hb2,
        const float* __restrict__ hW3, const float* __restrict__ hb3,
        float* __restrict__ out) {
    __shared__ float sf[8*128], s1[8*128], s2[8*64];
    int t = threadIdx.x;
    for (int i = t; i < 1024; i += 128) sf[i] = g_final[i];
    __syncthreads();
    {
        int d = t;
        for (int b = 0; b < 8; b++) {
            float acc = hb1[d];
            for (int k = 0; k < 128; k++) acc += sf[b*128+k]*hW1[k*128+d];
            s1[b*128+d] = siluf_(acc);
        }
    }
    __syncthreads();
    if (t < 64) {
        int e = t;
        for (int b = 0; b < 8; b++) {
            float acc = hb2[e];
            for (int k = 0; k < 128; k++) acc += s1[b*128+k]*hW2[k*64+e];
            s2[b*64+e] = siluf_(acc);
        }
    }
    __syncthreads();
    if (t < 16) {
        int b = t >> 1, o = t & 1;
        float acc = hb3[o];
        for (int k = 0; k < 64; k++) acc += s2[b*64+k]*hW3[k*2+o];
        float sp = fmaxf(acc, 0.f) + log1pf(expf(-fabsf(acc)));
        out[b*2+o] = sp + 1e-6f;
    }
}

// ---------------- launch ----------------
extern "C" void kernel_launch(void* const* d_in, const int* in_sizes, int n_in,
                              void* d_out, int out_size) {
    const float* snap  = (const float*)d_in[0];
    const int*   ei    = (const int*)  d_in[1];
    const float* scale = (const float*)d_in[2];
    const float* shift = (const float*)d_in[3];
    const float* W1    = (const float*)d_in[4];
    const float* b1    = (const float*)d_in[5];
    const float* W2    = (const float*)d_in[6];
    const float* b2    = (const float*)d_in[7];
    const float* W3    = (const float*)d_in[8];
    const float* b3    = (const float*)d_in[9];
    const float* Wih0  = (const float*)d_in[10];
    const float* Whh0  = (const float*)d_in[11];
    const float* bih0  = (const float*)d_in[12];
    const float* bhh0  = (const float*)d_in[13];
    const float* Wih1  = (const float*)d_in[14];
    const float* Whh1  = (const float*)d_in[15];
    const float* bih1  = (const float*)d_in[16];
    const float* bhh1  = (const float*)d_in[17];
    const float* hW1   = (const float*)d_in[18];
    const float* hb1   = (const float*)d_in[19];
    const float* hW2   = (const float*)d_in[20];
    const float* hb2   = (const float*)d_in[21];
    const float* hW3   = (const float*)d_in[22];
    const float* hb3   = (const float*)d_in[23];
    float* out = (float*)d_out;

    const int megaSmem = (128*HST + 128*HST + 128*WST)*(int)sizeof(float); // 204800
    cudaFuncSetAttribute(k_mega, cudaFuncAttributeMaxDynamicSharedMemorySize, megaSmem);

    k_prep<<<1, 32>>>(ei);
    k_mega<<<Gc, 512, megaSmem>>>(snap, scale, shift, W1, b1, W2, b2, W3, b3);
    k_xg0<<<Gc/16, 512>>>(Wih0, bih0, bhh0);
    k_lstm4<<<Bc*CLN, 384>>>(Whh0, Wih1, Whh1, bih1, bhh1);
    k_head<<<1, 128>>>(hW1, hb1, hW2, hb2, hW3, hb3, out);
}